// round 2
// baseline (speedup 1.0000x reference)
#include <cuda_runtime.h>
#include <math.h>

#define NN 50000
#define EE 800000
#define IND 256
#define HH 4
#define CC 64
#define HC 256   // H*C
#define LAT 32
#define EDIM 3

// ---------------- scratch (device globals; no allocation allowed) ----------------
__device__ int   g_deg[NN];
__device__ int   g_off[NN + 1];
__device__ int   g_cnt[NN];
__device__ int   g_csr[EE];
__device__ float g_loop[NN * EDIM];
__device__ float g_xl[NN * HC];
__device__ float g_xr[NN * HC];
__device__ float g_h1[NN * CC];
__device__ float g_h2[NN * CC];

// ---------------- CSR build ----------------
__global__ void deg_kernel(const int* __restrict__ dst, int e) {
    int i = blockIdx.x * blockDim.x + threadIdx.x;
    if (i < e) atomicAdd(&g_deg[dst[i]], 1);
}

__global__ void scan_kernel(int n) {
    __shared__ int tmp[1024];
    __shared__ int carry;
    int tid = threadIdx.x;
    if (tid == 0) { carry = 0; g_off[0] = 0; }
    __syncthreads();
    for (int base = 0; base < n; base += 1024) {
        int i = base + tid;
        int v = (i < n) ? g_deg[i] : 0;
        tmp[tid] = v;
        __syncthreads();
        for (int d = 1; d < 1024; d <<= 1) {
            int t = (tid >= d) ? tmp[tid - d] : 0;
            __syncthreads();
            tmp[tid] += t;
            __syncthreads();
        }
        int incl = tmp[tid];
        int c = carry;
        if (i < n) g_off[i + 1] = c + incl;
        __syncthreads();
        if (tid == 1023) carry = c + incl;
        __syncthreads();
    }
}

__global__ void scatter_kernel(const int* __restrict__ dst, int e) {
    int i = blockIdx.x * blockDim.x + threadIdx.x;
    if (i < e) {
        int d = dst[i];
        int p = g_off[d] + atomicAdd(&g_cnt[d], 1);
        g_csr[p] = i;
    }
}

__global__ void loopattr_kernel(const int* __restrict__ dst,
                                const float* __restrict__ ea, int e) {
    int i = blockIdx.x * blockDim.x + threadIdx.x;
    if (i < e) {
        int d = dst[i];
        atomicAdd(&g_loop[d * 3 + 0], ea[i * 3 + 0]);
        atomicAdd(&g_loop[d * 3 + 1], ea[i * 3 + 1]);
        atomicAdd(&g_loop[d * 3 + 2], ea[i * 3 + 2]);
    }
}

__global__ void loopdiv_kernel(int n) {
    int i = blockIdx.x * blockDim.x + threadIdx.x;
    if (i < n) {
        float inv = 1.0f / (float)max(g_deg[i], 1);
        g_loop[i * 3 + 0] *= inv;
        g_loop[i * 3 + 1] *= inv;
        g_loop[i * 3 + 2] *= inv;
    }
}

// ---------------- tiled SGEMM: C[M,Nc] = A[M,K] @ B[K,Nc] + bias ----------------
// BM=BN=64, BK=16, 256 threads, 4x4 per thread.
__global__ void sgemm_bias(const float* __restrict__ A, const float* __restrict__ B,
                           const float* __restrict__ bias, float* __restrict__ C,
                           int M, int K, int Nc) {
    __shared__ float As[16][64];
    __shared__ float Bs[16][64 + 4];
    int tid = threadIdx.x;
    int tx = tid & 15, ty = tid >> 4;
    int row0 = blockIdx.y * 64, col0 = blockIdx.x * 64;
    float acc[4][4] = {};
    for (int k0 = 0; k0 < K; k0 += 16) {
        // load A tile 64x16 (row-major A)
        #pragma unroll
        for (int i = tid; i < 64 * 16; i += 256) {
            int m = i >> 4, k = i & 15;
            int r = row0 + m;
            As[k][m] = (r < M) ? A[(long)r * K + k0 + k] : 0.0f;
        }
        // load B tile 16x64
        #pragma unroll
        for (int i = tid; i < 16 * 64; i += 256) {
            int k = i >> 6, c = i & 63;
            int cc = col0 + c;
            Bs[k][c] = (cc < Nc) ? B[(long)(k0 + k) * Nc + cc] : 0.0f;
        }
        __syncthreads();
        #pragma unroll
        for (int k = 0; k < 16; k++) {
            float a[4], b[4];
            #pragma unroll
            for (int i = 0; i < 4; i++) a[i] = As[k][ty * 4 + i];
            #pragma unroll
            for (int j = 0; j < 4; j++) b[j] = Bs[k][tx * 4 + j];
            #pragma unroll
            for (int i = 0; i < 4; i++)
                #pragma unroll
                for (int j = 0; j < 4; j++)
                    acc[i][j] += a[i] * b[j];
        }
        __syncthreads();
    }
    #pragma unroll
    for (int i = 0; i < 4; i++) {
        int r = row0 + ty * 4 + i;
        if (r >= M) continue;
        #pragma unroll
        for (int j = 0; j < 4; j++) {
            int c = col0 + tx * 4 + j;
            if (c < Nc) C[(long)r * Nc + c] = acc[i][j] + bias[c];
        }
    }
}

// ---------------- fused GATv2 attention + aggregation (one warp per dst node) ----
// out[n,c] = relu( mean_h( sum_e softmax_e(alpha) * xl[src,h,c] ) + bias[c] )
__global__ void gat_agg(const float* __restrict__ xl, const float* __restrict__ xr,
                        const int* __restrict__ src, const float* __restrict__ eattr,
                        const float* __restrict__ We, const float* __restrict__ att,
                        const float* __restrict__ bias, float* __restrict__ out,
                        int n) {
    int warp = (blockIdx.x * blockDim.x + threadIdx.x) >> 5;
    int lane = threadIdx.x & 31;
    if (warp >= n) return;
    int node = warp;

    float we0[8], we1[8], we2[8], attv[8], xrv[8];
    #pragma unroll
    for (int k = 0; k < 8; k++) {
        int j = lane + 32 * k;
        we0[k] = We[j];
        we1[k] = We[256 + j];
        we2[k] = We[512 + j];
        attv[k] = att[j];
        xrv[k] = xr[(long)node * HC + j];
    }

    float m[4] = {-1e30f, -1e30f, -1e30f, -1e30f};
    float s[4] = {0.f, 0.f, 0.f, 0.f};
    float acc[8] = {0.f, 0.f, 0.f, 0.f, 0.f, 0.f, 0.f, 0.f};

    int o0 = g_off[node];
    int deg = g_off[node + 1] - o0;

    for (int i = 0; i <= deg; i++) {
        int sn;
        float ea0, ea1, ea2;
        if (i == deg) {  // self loop
            sn = node;
            ea0 = g_loop[node * 3 + 0];
            ea1 = g_loop[node * 3 + 1];
            ea2 = g_loop[node * 3 + 2];
        } else {
            int eid = g_csr[o0 + i];
            sn = src[eid];
            ea0 = eattr[eid * 3 + 0];
            ea1 = eattr[eid * 3 + 1];
            ea2 = eattr[eid * 3 + 2];
        }
        const float* xp = xl + (long)sn * HC + lane;
        float xv[8];
        #pragma unroll
        for (int k = 0; k < 8; k++) xv[k] = xp[32 * k];

        float p[4] = {0.f, 0.f, 0.f, 0.f};
        #pragma unroll
        for (int k = 0; k < 8; k++) {
            float t = xv[k] + xrv[k] + ea0 * we0[k] + ea1 * we1[k] + ea2 * we2[k];
            t = (t > 0.f) ? t : 0.2f * t;
            p[k >> 1] += t * attv[k];
        }
        #pragma unroll
        for (int o = 16; o; o >>= 1) {
            p[0] += __shfl_xor_sync(0xffffffffu, p[0], o);
            p[1] += __shfl_xor_sync(0xffffffffu, p[1], o);
            p[2] += __shfl_xor_sync(0xffffffffu, p[2], o);
            p[3] += __shfl_xor_sync(0xffffffffu, p[3], o);
        }
        #pragma unroll
        for (int h = 0; h < 4; h++) {
            float a = p[h];
            float nm = fmaxf(m[h], a);
            float sc = __expf(m[h] - nm);
            float w  = __expf(a - nm);
            s[h] = s[h] * sc + w;
            m[h] = nm;
            acc[2 * h]     = acc[2 * h] * sc     + w * xv[2 * h];
            acc[2 * h + 1] = acc[2 * h + 1] * sc + w * xv[2 * h + 1];
        }
    }

    float r0 = 0.25f * (acc[0] / s[0] + acc[2] / s[1] + acc[4] / s[2] + acc[6] / s[3]) + bias[lane];
    float r1 = 0.25f * (acc[1] / s[0] + acc[3] / s[1] + acc[5] / s[2] + acc[7] / s[3]) + bias[lane + 32];
    r0 = fmaxf(r0, 0.f);
    r1 = fmaxf(r1, 0.f);
    out[(long)node * CC + lane] = r0;
    out[(long)node * CC + lane + 32] = r1;
}

// ---------------- launch ----------------
extern "C" void kernel_launch(void* const* d_in, const int* in_sizes, int n_in,
                              void* d_out, int out_size) {
    const float* x          = (const float*)d_in[0];
    const int*   edge_index = (const int*)d_in[1];
    const float* edge_attr  = (const float*)d_in[2];
    const float* Wl0  = (const float*)d_in[3];
    const float* bl0  = (const float*)d_in[4];
    const float* Wr0  = (const float*)d_in[5];
    const float* br0  = (const float*)d_in[6];
    const float* We0  = (const float*)d_in[7];
    const float* att0 = (const float*)d_in[8];
    const float* bias0= (const float*)d_in[9];
    const float* Wl1  = (const float*)d_in[10];
    const float* bl1  = (const float*)d_in[11];
    const float* Wr1  = (const float*)d_in[12];
    const float* br1  = (const float*)d_in[13];
    const float* We1  = (const float*)d_in[14];
    const float* att1 = (const float*)d_in[15];
    const float* bias1= (const float*)d_in[16];
    const float* Wmu  = (const float*)d_in[17];
    const float* bmu  = (const float*)d_in[18];

    const int E = in_sizes[1] / 2;
    const int n = in_sizes[0] / IND;
    const int* src = edge_index;
    const int* dst = edge_index + E;

    void *p_deg, *p_cnt, *p_loop, *p_xl, *p_xr, *p_h1, *p_h2;
    cudaGetSymbolAddress(&p_deg, g_deg);
    cudaGetSymbolAddress(&p_cnt, g_cnt);
    cudaGetSymbolAddress(&p_loop, g_loop);
    cudaGetSymbolAddress(&p_xl, g_xl);
    cudaGetSymbolAddress(&p_xr, g_xr);
    cudaGetSymbolAddress(&p_h1, g_h1);
    cudaGetSymbolAddress(&p_h2, g_h2);

    cudaMemsetAsync(p_deg, 0, (size_t)n * sizeof(int));
    cudaMemsetAsync(p_cnt, 0, (size_t)n * sizeof(int));
    cudaMemsetAsync(p_loop, 0, (size_t)n * EDIM * sizeof(float));

    int eb = (E + 255) / 256;
    int nb = (n + 255) / 256;

    // CSR by destination + self-loop edge attr (graph shared by both layers)
    deg_kernel<<<eb, 256>>>(dst, E);
    scan_kernel<<<1, 1024>>>(n);
    scatter_kernel<<<eb, 256>>>(dst, E);
    loopattr_kernel<<<eb, 256>>>(dst, edge_attr, E);
    loopdiv_kernel<<<nb, 256>>>(n);

    dim3 g0((HC + 63) / 64, (n + 63) / 64);
    int aggBlocks = (n * 32 + 255) / 256;

    // ---- layer 0 ----
    sgemm_bias<<<g0, 256>>>(x, Wl0, bl0, (float*)p_xl, n, IND, HC);
    sgemm_bias<<<g0, 256>>>(x, Wr0, br0, (float*)p_xr, n, IND, HC);
    gat_agg<<<aggBlocks, 256>>>((const float*)p_xl, (const float*)p_xr,
                                src, edge_attr, We0, att0, bias0,
                                (float*)p_h1, n);

    // ---- layer 1 ----
    sgemm_bias<<<g0, 256>>>((const float*)p_h1, Wl1, bl1, (float*)p_xl, n, CC, HC);
    sgemm_bias<<<g0, 256>>>((const float*)p_h1, Wr1, br1, (float*)p_xr, n, CC, HC);
    gat_agg<<<aggBlocks, 256>>>((const float*)p_xl, (const float*)p_xr,
                                src, edge_attr, We1, att1, bias1,
                                (float*)p_h2, n);

    // ---- final projection ----
    dim3 gmu((LAT + 63) / 64, (n + 63) / 64);
    sgemm_bias<<<gmu, 256>>>((const float*)p_h2, Wmu, bmu, (float*)d_out, n, CC, LAT);
}

// round 3
// speedup vs baseline: 1.5327x; 1.5327x over previous
#include <cuda_runtime.h>
#include <math.h>

#define NN 50000
#define EE 800000
#define IND 256
#define HH 4
#define CC 64
#define HC 256   // H*C
#define LAT 32
#define EDIM 3

// ---------------- scratch (device globals; no allocation allowed) ----------------
__device__ int   g_deg[NN];
__device__ int   g_off[NN + 1];
__device__ int   g_cnt[NN];
__device__ int   g_csr[EE];
__device__ float g_loop[NN * EDIM];
__device__ float g_xl[NN * HC];
__device__ float g_xr[NN * HC];
__device__ float g_h1[NN * CC];
__device__ float g_h2[NN * CC];

// ---------------- CSR build ----------------
__global__ void deg_kernel(const int* __restrict__ dst, int e) {
    int i = blockIdx.x * blockDim.x + threadIdx.x;
    if (i < e) atomicAdd(&g_deg[dst[i]], 1);
}

__global__ void scan_kernel(int n) {
    __shared__ int tmp[1024];
    __shared__ int carry;
    int tid = threadIdx.x;
    if (tid == 0) { carry = 0; g_off[0] = 0; }
    __syncthreads();
    for (int base = 0; base < n; base += 1024) {
        int i = base + tid;
        int v = (i < n) ? g_deg[i] : 0;
        tmp[tid] = v;
        __syncthreads();
        for (int d = 1; d < 1024; d <<= 1) {
            int t = (tid >= d) ? tmp[tid - d] : 0;
            __syncthreads();
            tmp[tid] += t;
            __syncthreads();
        }
        int incl = tmp[tid];
        int c = carry;
        if (i < n) g_off[i + 1] = c + incl;
        __syncthreads();
        if (tid == 1023) carry = c + incl;
        __syncthreads();
    }
}

__global__ void scatter_kernel(const int* __restrict__ dst, int e) {
    int i = blockIdx.x * blockDim.x + threadIdx.x;
    if (i < e) {
        int d = dst[i];
        int p = g_off[d] + atomicAdd(&g_cnt[d], 1);
        g_csr[p] = i;
    }
}

__global__ void loopattr_kernel(const int* __restrict__ dst,
                                const float* __restrict__ ea, int e) {
    int i = blockIdx.x * blockDim.x + threadIdx.x;
    if (i < e) {
        int d = dst[i];
        atomicAdd(&g_loop[d * 3 + 0], ea[i * 3 + 0]);
        atomicAdd(&g_loop[d * 3 + 1], ea[i * 3 + 1]);
        atomicAdd(&g_loop[d * 3 + 2], ea[i * 3 + 2]);
    }
}

__global__ void loopdiv_kernel(int n) {
    int i = blockIdx.x * blockDim.x + threadIdx.x;
    if (i < n) {
        float inv = 1.0f / (float)max(g_deg[i], 1);
        g_loop[i * 3 + 0] *= inv;
        g_loop[i * 3 + 1] *= inv;
        g_loop[i * 3 + 2] *= inv;
    }
}

// ---------------- TF32 tensor-core GEMM ----------------
// Computes [Cl | Cr] = A[M,K] @ [Bl | Br] (+ [bl | br]), Bl/Br are [K,256].
// CTA tile 128x128, 8 warps (2x4), warp tile 64x32, mma m16n8k8 tf32.
__device__ __forceinline__ unsigned f2tf32(float f) {
    unsigned u;
    asm("cvt.rna.tf32.f32 %0, %1;" : "=r"(u) : "f"(f));
    return u;
}

__global__ __launch_bounds__(256) void gemm_tf32_dual(
    const float* __restrict__ A,
    const float* __restrict__ Bl, const float* __restrict__ Br,
    const float* __restrict__ bl, const float* __restrict__ br,
    float* __restrict__ Cl, float* __restrict__ Cr,
    int M, int K)
{
    __shared__ unsigned As[32][136];
    __shared__ unsigned Bs[32][136];

    const int tid  = threadIdx.x;
    const int lane = tid & 31;
    const int warp = tid >> 5;
    const int g = lane >> 2;    // groupID
    const int q = lane & 3;     // threadID in group

    const int wm = warp & 1;        // 2 warps along M
    const int wn = warp >> 1;       // 4 warps along N
    const int m_warp = wm * 64;
    const int n_warp = wn * 32;

    const int row0 = blockIdx.y * 128;
    const int col0 = blockIdx.x * 128;          // 0,128 -> left; 256,384 -> right
    const int half = (col0 >= 256);
    const float* Bp = half ? Br : Bl;
    const float* biasp = half ? br : bl;
    float* Cp = half ? Cr : Cl;
    const int bcol0 = col0 - half * 256;

    float acc[4][4][4] = {};

    for (int k0 = 0; k0 < K; k0 += 32) {
        // ---- load A tile 128x32 (store k-major, tf32) ----
        #pragma unroll
        for (int it = 0; it < 4; it++) {
            int idx = tid + it * 256;           // 1024 float4 slots
            int r = idx >> 3, c4 = idx & 7;
            int gr = row0 + r;
            float4 v = make_float4(0.f, 0.f, 0.f, 0.f);
            if (gr < M)
                v = *reinterpret_cast<const float4*>(A + (long)gr * K + k0 + c4 * 4);
            As[c4 * 4 + 0][r] = f2tf32(v.x);
            As[c4 * 4 + 1][r] = f2tf32(v.y);
            As[c4 * 4 + 2][r] = f2tf32(v.z);
            As[c4 * 4 + 3][r] = f2tf32(v.w);
        }
        // ---- load B tile 32x128 ----
        #pragma unroll
        for (int it = 0; it < 4; it++) {
            int idx = tid + it * 256;           // 1024 float4 slots
            int r = idx >> 5, c4 = idx & 31;
            float4 v = *reinterpret_cast<const float4*>(Bp + (long)(k0 + r) * 256 + bcol0 + c4 * 4);
            uint4 u;
            u.x = f2tf32(v.x); u.y = f2tf32(v.y);
            u.z = f2tf32(v.z); u.w = f2tf32(v.w);
            *reinterpret_cast<uint4*>(&Bs[r][c4 * 4]) = u;
        }
        __syncthreads();

        #pragma unroll
        for (int kk = 0; kk < 32; kk += 8) {
            unsigned a[4][4], b[4][2];
            #pragma unroll
            for (int i = 0; i < 4; i++) {
                int r = m_warp + i * 16 + g;
                a[i][0] = As[kk + q][r];
                a[i][1] = As[kk + q][r + 8];
                a[i][2] = As[kk + q + 4][r];
                a[i][3] = As[kk + q + 4][r + 8];
            }
            #pragma unroll
            for (int j = 0; j < 4; j++) {
                int c = n_warp + j * 8 + g;
                b[j][0] = Bs[kk + q][c];
                b[j][1] = Bs[kk + q + 4][c];
            }
            #pragma unroll
            for (int i = 0; i < 4; i++)
                #pragma unroll
                for (int j = 0; j < 4; j++) {
                    asm volatile(
                        "mma.sync.aligned.m16n8k8.row.col.f32.tf32.tf32.f32 "
                        "{%0,%1,%2,%3}, {%4,%5,%6,%7}, {%8,%9}, {%0,%1,%2,%3};"
                        : "+f"(acc[i][j][0]), "+f"(acc[i][j][1]),
                          "+f"(acc[i][j][2]), "+f"(acc[i][j][3])
                        : "r"(a[i][0]), "r"(a[i][1]), "r"(a[i][2]), "r"(a[i][3]),
                          "r"(b[j][0]), "r"(b[j][1]));
                }
        }
        __syncthreads();
    }

    // ---- epilogue ----
    #pragma unroll
    for (int i = 0; i < 4; i++) {
        int r0 = row0 + m_warp + i * 16 + g;
        #pragma unroll
        for (int j = 0; j < 4; j++) {
            int cl = bcol0 + n_warp + j * 8 + 2 * q;
            float b0 = biasp[cl], b1 = biasp[cl + 1];
            if (r0 < M) {
                Cp[(long)r0 * 256 + cl]     = acc[i][j][0] + b0;
                Cp[(long)r0 * 256 + cl + 1] = acc[i][j][1] + b1;
            }
            if (r0 + 8 < M) {
                Cp[(long)(r0 + 8) * 256 + cl]     = acc[i][j][2] + b0;
                Cp[(long)(r0 + 8) * 256 + cl + 1] = acc[i][j][3] + b1;
            }
        }
    }
}

// ---------------- fp32 tiled SGEMM (final projection only) ----------------
__global__ void sgemm_bias(const float* __restrict__ A, const float* __restrict__ B,
                           const float* __restrict__ bias, float* __restrict__ C,
                           int M, int K, int Nc) {
    __shared__ float As[16][64];
    __shared__ float Bs[16][64 + 4];
    int tid = threadIdx.x;
    int tx = tid & 15, ty = tid >> 4;
    int row0 = blockIdx.y * 64, col0 = blockIdx.x * 64;
    float acc[4][4] = {};
    for (int k0 = 0; k0 < K; k0 += 16) {
        #pragma unroll
        for (int i = tid; i < 64 * 16; i += 256) {
            int m = i >> 4, k = i & 15;
            int r = row0 + m;
            As[k][m] = (r < M) ? A[(long)r * K + k0 + k] : 0.0f;
        }
        #pragma unroll
        for (int i = tid; i < 16 * 64; i += 256) {
            int k = i >> 6, c = i & 63;
            int cc = col0 + c;
            Bs[k][c] = (cc < Nc) ? B[(long)(k0 + k) * Nc + cc] : 0.0f;
        }
        __syncthreads();
        #pragma unroll
        for (int k = 0; k < 16; k++) {
            float a[4], b[4];
            #pragma unroll
            for (int i = 0; i < 4; i++) a[i] = As[k][ty * 4 + i];
            #pragma unroll
            for (int j = 0; j < 4; j++) b[j] = Bs[k][tx * 4 + j];
            #pragma unroll
            for (int i = 0; i < 4; i++)
                #pragma unroll
                for (int j = 0; j < 4; j++)
                    acc[i][j] += a[i] * b[j];
        }
        __syncthreads();
    }
    #pragma unroll
    for (int i = 0; i < 4; i++) {
        int r = row0 + ty * 4 + i;
        if (r >= M) continue;
        #pragma unroll
        for (int j = 0; j < 4; j++) {
            int c = col0 + tx * 4 + j;
            if (c < Nc) C[(long)r * Nc + c] = acc[i][j] + bias[c];
        }
    }
}

// ---------------- fused GATv2 attention + aggregation (one warp per dst node) ----
__global__ void gat_agg(const float* __restrict__ xl, const float* __restrict__ xr,
                        const int* __restrict__ src, const float* __restrict__ eattr,
                        const float* __restrict__ We, const float* __restrict__ att,
                        const float* __restrict__ bias, float* __restrict__ out,
                        int n) {
    int warp = (blockIdx.x * blockDim.x + threadIdx.x) >> 5;
    int lane = threadIdx.x & 31;
    if (warp >= n) return;
    int node = warp;

    float we0[8], we1[8], we2[8], attv[8], xrv[8];
    #pragma unroll
    for (int k = 0; k < 8; k++) {
        int j = lane + 32 * k;
        we0[k] = We[j];
        we1[k] = We[256 + j];
        we2[k] = We[512 + j];
        attv[k] = att[j];
        xrv[k] = xr[(long)node * HC + j];
    }

    float m[4] = {-1e30f, -1e30f, -1e30f, -1e30f};
    float s[4] = {0.f, 0.f, 0.f, 0.f};
    float acc[8] = {0.f, 0.f, 0.f, 0.f, 0.f, 0.f, 0.f, 0.f};

    int o0 = g_off[node];
    int deg = g_off[node + 1] - o0;

    for (int i = 0; i <= deg; i++) {
        int sn;
        float ea0, ea1, ea2;
        if (i == deg) {  // self loop
            sn = node;
            ea0 = g_loop[node * 3 + 0];
            ea1 = g_loop[node * 3 + 1];
            ea2 = g_loop[node * 3 + 2];
        } else {
            int eid = g_csr[o0 + i];
            sn = src[eid];
            ea0 = eattr[eid * 3 + 0];
            ea1 = eattr[eid * 3 + 1];
            ea2 = eattr[eid * 3 + 2];
        }
        const float* xp = xl + (long)sn * HC + lane;
        float xv[8];
        #pragma unroll
        for (int k = 0; k < 8; k++) xv[k] = xp[32 * k];

        float p[4] = {0.f, 0.f, 0.f, 0.f};
        #pragma unroll
        for (int k = 0; k < 8; k++) {
            float t = xv[k] + xrv[k] + ea0 * we0[k] + ea1 * we1[k] + ea2 * we2[k];
            t = (t > 0.f) ? t : 0.2f * t;
            p[k >> 1] += t * attv[k];
        }
        #pragma unroll
        for (int o = 16; o; o >>= 1) {
            p[0] += __shfl_xor_sync(0xffffffffu, p[0], o);
            p[1] += __shfl_xor_sync(0xffffffffu, p[1], o);
            p[2] += __shfl_xor_sync(0xffffffffu, p[2], o);
            p[3] += __shfl_xor_sync(0xffffffffu, p[3], o);
        }
        #pragma unroll
        for (int h = 0; h < 4; h++) {
            float a = p[h];
            float nm = fmaxf(m[h], a);
            float sc = __expf(m[h] - nm);
            float w  = __expf(a - nm);
            s[h] = s[h] * sc + w;
            m[h] = nm;
            acc[2 * h]     = acc[2 * h] * sc     + w * xv[2 * h];
            acc[2 * h + 1] = acc[2 * h + 1] * sc + w * xv[2 * h + 1];
        }
    }

    float r0 = 0.25f * (acc[0] / s[0] + acc[2] / s[1] + acc[4] / s[2] + acc[6] / s[3]) + bias[lane];
    float r1 = 0.25f * (acc[1] / s[0] + acc[3] / s[1] + acc[5] / s[2] + acc[7] / s[3]) + bias[lane + 32];
    r0 = fmaxf(r0, 0.f);
    r1 = fmaxf(r1, 0.f);
    out[(long)node * CC + lane] = r0;
    out[(long)node * CC + lane + 32] = r1;
}

// ---------------- launch ----------------
extern "C" void kernel_launch(void* const* d_in, const int* in_sizes, int n_in,
                              void* d_out, int out_size) {
    const float* x          = (const float*)d_in[0];
    const int*   edge_index = (const int*)d_in[1];
    const float* edge_attr  = (const float*)d_in[2];
    const float* Wl0  = (const float*)d_in[3];
    const float* bl0  = (const float*)d_in[4];
    const float* Wr0  = (const float*)d_in[5];
    const float* br0  = (const float*)d_in[6];
    const float* We0  = (const float*)d_in[7];
    const float* att0 = (const float*)d_in[8];
    const float* bias0= (const float*)d_in[9];
    const float* Wl1  = (const float*)d_in[10];
    const float* bl1  = (const float*)d_in[11];
    const float* Wr1  = (const float*)d_in[12];
    const float* br1  = (const float*)d_in[13];
    const float* We1  = (const float*)d_in[14];
    const float* att1 = (const float*)d_in[15];
    const float* bias1= (const float*)d_in[16];
    const float* Wmu  = (const float*)d_in[17];
    const float* bmu  = (const float*)d_in[18];

    const int E = in_sizes[1] / 2;
    const int n = in_sizes[0] / IND;
    const int* src = edge_index;
    const int* dst = edge_index + E;

    void *p_deg, *p_cnt, *p_loop, *p_xl, *p_xr, *p_h1, *p_h2;
    cudaGetSymbolAddress(&p_deg, g_deg);
    cudaGetSymbolAddress(&p_cnt, g_cnt);
    cudaGetSymbolAddress(&p_loop, g_loop);
    cudaGetSymbolAddress(&p_xl, g_xl);
    cudaGetSymbolAddress(&p_xr, g_xr);
    cudaGetSymbolAddress(&p_h1, g_h1);
    cudaGetSymbolAddress(&p_h2, g_h2);

    cudaMemsetAsync(p_deg, 0, (size_t)n * sizeof(int));
    cudaMemsetAsync(p_cnt, 0, (size_t)n * sizeof(int));
    cudaMemsetAsync(p_loop, 0, (size_t)n * EDIM * sizeof(float));

    int eb = (E + 255) / 256;
    int nb = (n + 255) / 256;

    // CSR by destination + self-loop edge attr (graph shared by both layers)
    deg_kernel<<<eb, 256>>>(dst, E);
    scan_kernel<<<1, 1024>>>(n);
    scatter_kernel<<<eb, 256>>>(dst, E);
    loopattr_kernel<<<eb, 256>>>(dst, edge_attr, E);
    loopdiv_kernel<<<nb, 256>>>(n);

    dim3 gdual(4, (n + 127) / 128);   // 512 logical cols / 128
    int aggBlocks = (n * 32 + 255) / 256;

    // ---- layer 0 ----
    gemm_tf32_dual<<<gdual, 256>>>(x, Wl0, Wr0, bl0, br0,
                                   (float*)p_xl, (float*)p_xr, n, IND);
    gat_agg<<<aggBlocks, 256>>>((const float*)p_xl, (const float*)p_xr,
                                src, edge_attr, We0, att0, bias0,
                                (float*)p_h1, n);

    // ---- layer 1 ----
    gemm_tf32_dual<<<gdual, 256>>>((const float*)p_h1, Wl1, Wr1, bl1, br1,
                                   (float*)p_xl, (float*)p_xr, n, CC);
    gat_agg<<<aggBlocks, 256>>>((const float*)p_xl, (const float*)p_xr,
                                src, edge_attr, We1, att1, bias1,
                                (float*)p_h2, n);

    // ---- final projection ----
    dim3 gmu((LAT + 63) / 64, (n + 63) / 64);
    sgemm_bias<<<gmu, 256>>>((const float*)p_h2, Wmu, bmu, (float*)d_out, n, CC, LAT);
}

// round 4
// speedup vs baseline: 1.9007x; 1.2401x over previous
#include <cuda_runtime.h>
#include <math.h>

#define NN 50000
#define EE 800000
#define IND 256
#define HH 4
#define CC 64
#define HC 256   // H*C
#define LAT 32
#define EDIM 3

// ---------------- scratch (device globals; no allocation allowed) ----------------
__device__ int   g_deg[NN];
__device__ int   g_off[NN + 1];
__device__ int   g_cnt[NN];
__device__ int   g_csr[EE];
__device__ int   g_bsum[64];
__device__ float g_loop[NN * EDIM];
__device__ float g_xl[NN * HC];
__device__ float g_xr[NN * HC];
__device__ float g_h1[NN * CC];
__device__ float g_h2[NN * CC];

// ---------------- CSR build ----------------
// fused: degree count + self-loop edge_attr accumulation
__global__ void edge_accum_kernel(const int* __restrict__ dst,
                                  const float* __restrict__ ea, int e) {
    int i = blockIdx.x * blockDim.x + threadIdx.x;
    if (i < e) {
        int d = dst[i];
        atomicAdd(&g_deg[d], 1);
        atomicAdd(&g_loop[d * 3 + 0], ea[i * 3 + 0]);
        atomicAdd(&g_loop[d * 3 + 1], ea[i * 3 + 1]);
        atomicAdd(&g_loop[d * 3 + 2], ea[i * 3 + 2]);
    }
}

// parallel scan: per-block inclusive scan of g_deg -> g_off[i+1], block sums -> g_bsum
__global__ void scan_block_kernel(int n) {
    __shared__ int tmp[1024];
    int tid = threadIdx.x;
    int i = blockIdx.x * 1024 + tid;
    int v = (i < n) ? g_deg[i] : 0;
    tmp[tid] = v;
    __syncthreads();
    for (int d = 1; d < 1024; d <<= 1) {
        int t = (tid >= d) ? tmp[tid - d] : 0;
        __syncthreads();
        tmp[tid] += t;
        __syncthreads();
    }
    if (i < n) g_off[i + 1] = tmp[tid];
    if (tid == 1023) g_bsum[blockIdx.x] = tmp[tid];
    if (i == 0) g_off[0] = 0;
}

__global__ void scan_bsum_kernel(int nb) {
    __shared__ int tmp[64];
    int tid = threadIdx.x;
    int v = (tid < nb) ? g_bsum[tid] : 0;
    tmp[tid] = v;
    __syncthreads();
    for (int d = 1; d < 64; d <<= 1) {
        int t = (tid >= d) ? tmp[tid - d] : 0;
        __syncthreads();
        tmp[tid] += t;
        __syncthreads();
    }
    if (tid < nb) g_bsum[tid] = tmp[tid] - v;  // exclusive
}

__global__ void scan_add_kernel(int n) {
    if (blockIdx.x == 0) return;
    int i = blockIdx.x * 1024 + threadIdx.x;
    if (i < n) g_off[i + 1] += g_bsum[blockIdx.x];
}

__global__ void scatter_kernel(const int* __restrict__ dst, int e) {
    int i = blockIdx.x * blockDim.x + threadIdx.x;
    if (i < e) {
        int d = dst[i];
        int p = g_off[d] + atomicAdd(&g_cnt[d], 1);
        g_csr[p] = i;
    }
}

__global__ void loopdiv_kernel(int n) {
    int i = blockIdx.x * blockDim.x + threadIdx.x;
    if (i < n) {
        float inv = 1.0f / (float)max(g_deg[i], 1);
        g_loop[i * 3 + 0] *= inv;
        g_loop[i * 3 + 1] *= inv;
        g_loop[i * 3 + 2] *= inv;
    }
}

// ---------------- TF32 tensor-core GEMM ----------------
__device__ __forceinline__ unsigned f2tf32(float f) {
    unsigned u;
    asm("cvt.rna.tf32.f32 %0, %1;" : "=r"(u) : "f"(f));
    return u;
}

__global__ __launch_bounds__(256) void gemm_tf32_dual(
    const float* __restrict__ A,
    const float* __restrict__ Bl, const float* __restrict__ Br,
    const float* __restrict__ bl, const float* __restrict__ br,
    float* __restrict__ Cl, float* __restrict__ Cr,
    int M, int K)
{
    __shared__ unsigned As[32][136];
    __shared__ unsigned Bs[32][136];

    const int tid  = threadIdx.x;
    const int lane = tid & 31;
    const int warp = tid >> 5;
    const int g = lane >> 2;
    const int q = lane & 3;

    const int wm = warp & 1;
    const int wn = warp >> 1;
    const int m_warp = wm * 64;
    const int n_warp = wn * 32;

    const int row0 = blockIdx.y * 128;
    const int col0 = blockIdx.x * 128;
    const int half = (col0 >= 256);
    const float* Bp = half ? Br : Bl;
    const float* biasp = half ? br : bl;
    float* Cp = half ? Cr : Cl;
    const int bcol0 = col0 - half * 256;

    float acc[4][4][4] = {};

    for (int k0 = 0; k0 < K; k0 += 32) {
        #pragma unroll
        for (int it = 0; it < 4; it++) {
            int idx = tid + it * 256;
            int r = idx >> 3, c4 = idx & 7;
            int gr = row0 + r;
            float4 v = make_float4(0.f, 0.f, 0.f, 0.f);
            if (gr < M)
                v = *reinterpret_cast<const float4*>(A + (long)gr * K + k0 + c4 * 4);
            As[c4 * 4 + 0][r] = f2tf32(v.x);
            As[c4 * 4 + 1][r] = f2tf32(v.y);
            As[c4 * 4 + 2][r] = f2tf32(v.z);
            As[c4 * 4 + 3][r] = f2tf32(v.w);
        }
        #pragma unroll
        for (int it = 0; it < 4; it++) {
            int idx = tid + it * 256;
            int r = idx >> 5, c4 = idx & 31;
            float4 v = *reinterpret_cast<const float4*>(Bp + (long)(k0 + r) * 256 + bcol0 + c4 * 4);
            uint4 u;
            u.x = f2tf32(v.x); u.y = f2tf32(v.y);
            u.z = f2tf32(v.z); u.w = f2tf32(v.w);
            *reinterpret_cast<uint4*>(&Bs[r][c4 * 4]) = u;
        }
        __syncthreads();

        #pragma unroll
        for (int kk = 0; kk < 32; kk += 8) {
            unsigned a[4][4], b[4][2];
            #pragma unroll
            for (int i = 0; i < 4; i++) {
                int r = m_warp + i * 16 + g;
                a[i][0] = As[kk + q][r];
                a[i][1] = As[kk + q][r + 8];
                a[i][2] = As[kk + q + 4][r];
                a[i][3] = As[kk + q + 4][r + 8];
            }
            #pragma unroll
            for (int j = 0; j < 4; j++) {
                int c = n_warp + j * 8 + g;
                b[j][0] = Bs[kk + q][c];
                b[j][1] = Bs[kk + q + 4][c];
            }
            #pragma unroll
            for (int i = 0; i < 4; i++)
                #pragma unroll
                for (int j = 0; j < 4; j++) {
                    asm volatile(
                        "mma.sync.aligned.m16n8k8.row.col.f32.tf32.tf32.f32 "
                        "{%0,%1,%2,%3}, {%4,%5,%6,%7}, {%8,%9}, {%0,%1,%2,%3};"
                        : "+f"(acc[i][j][0]), "+f"(acc[i][j][1]),
                          "+f"(acc[i][j][2]), "+f"(acc[i][j][3])
                        : "r"(a[i][0]), "r"(a[i][1]), "r"(a[i][2]), "r"(a[i][3]),
                          "r"(b[j][0]), "r"(b[j][1]));
                }
        }
        __syncthreads();
    }

    #pragma unroll
    for (int i = 0; i < 4; i++) {
        int r0 = row0 + m_warp + i * 16 + g;
        #pragma unroll
        for (int j = 0; j < 4; j++) {
            int cl = bcol0 + n_warp + j * 8 + 2 * q;
            float b0 = biasp[cl], b1 = biasp[cl + 1];
            if (r0 < M) {
                Cp[(long)r0 * 256 + cl]     = acc[i][j][0] + b0;
                Cp[(long)r0 * 256 + cl + 1] = acc[i][j][1] + b1;
            }
            if (r0 + 8 < M) {
                Cp[(long)(r0 + 8) * 256 + cl]     = acc[i][j][2] + b0;
                Cp[(long)(r0 + 8) * 256 + cl + 1] = acc[i][j][3] + b1;
            }
        }
    }
}

// ---------------- fp32 tiled SGEMM (final projection only) ----------------
__global__ void sgemm_bias(const float* __restrict__ A, const float* __restrict__ B,
                           const float* __restrict__ bias, float* __restrict__ C,
                           int M, int K, int Nc) {
    __shared__ float As[16][64];
    __shared__ float Bs[16][64 + 4];
    int tid = threadIdx.x;
    int tx = tid & 15, ty = tid >> 4;
    int row0 = blockIdx.y * 64, col0 = blockIdx.x * 64;
    float acc[4][4] = {};
    for (int k0 = 0; k0 < K; k0 += 16) {
        #pragma unroll
        for (int i = tid; i < 64 * 16; i += 256) {
            int m = i >> 4, k = i & 15;
            int r = row0 + m;
            As[k][m] = (r < M) ? A[(long)r * K + k0 + k] : 0.0f;
        }
        #pragma unroll
        for (int i = tid; i < 16 * 64; i += 256) {
            int k = i >> 6, c = i & 63;
            int cc = col0 + c;
            Bs[k][c] = (cc < Nc) ? B[(long)(k0 + k) * Nc + cc] : 0.0f;
        }
        __syncthreads();
        #pragma unroll
        for (int k = 0; k < 16; k++) {
            float a[4], b[4];
            #pragma unroll
            for (int i = 0; i < 4; i++) a[i] = As[k][ty * 4 + i];
            #pragma unroll
            for (int j = 0; j < 4; j++) b[j] = Bs[k][tx * 4 + j];
            #pragma unroll
            for (int i = 0; i < 4; i++)
                #pragma unroll
                for (int j = 0; j < 4; j++)
                    acc[i][j] += a[i] * b[j];
        }
        __syncthreads();
    }
    #pragma unroll
    for (int i = 0; i < 4; i++) {
        int r = row0 + ty * 4 + i;
        if (r >= M) continue;
        #pragma unroll
        for (int j = 0; j < 4; j++) {
            int c = col0 + tx * 4 + j;
            if (c < Nc) C[(long)r * Nc + c] = acc[i][j] + bias[c];
        }
    }
}

// ---------------- fused GATv2 attention + aggregation ----------------
// One warp per dst node. Lane l owns 8 contiguous channels of head h=l>>3:
// channels base..base+7 where base = h*64 + (l&7)*8.
// Per edge: 2x LDG.128 gather, 3 shfl head-group reduce, 2 MUFU online softmax.
__global__ void gat_agg(const float* __restrict__ xl, const float* __restrict__ xr,
                        const int* __restrict__ src, const float* __restrict__ eattr,
                        const float* __restrict__ We, const float* __restrict__ att,
                        const float* __restrict__ bias, float* __restrict__ out,
                        int n) {
    int warp = (blockIdx.x * blockDim.x + threadIdx.x) >> 5;
    int lane = threadIdx.x & 31;
    if (warp >= n) return;
    const int node = warp;
    const int base = ((lane >> 3) << 6) | ((lane & 7) << 3);
    const int b4 = base >> 2;   // float4 index within a 256-float row

    float we0[8], we1[8], we2[8], attv[8], xrv[8];
    {
        const float4* We4 = (const float4*)We;
        const float4* at4 = (const float4*)att;
        const float4* xr4 = (const float4*)(xr + (long)node * HC);
        *(float4*)&we0[0] = We4[b4];        *(float4*)&we0[4] = We4[b4 + 1];
        *(float4*)&we1[0] = We4[64 + b4];   *(float4*)&we1[4] = We4[64 + b4 + 1];
        *(float4*)&we2[0] = We4[128 + b4];  *(float4*)&we2[4] = We4[128 + b4 + 1];
        *(float4*)&attv[0] = at4[b4];       *(float4*)&attv[4] = at4[b4 + 1];
        *(float4*)&xrv[0] = xr4[b4];        *(float4*)&xrv[4] = xr4[b4 + 1];
    }

    float m = -1e30f, s = 0.f;
    float acc[8] = {0.f, 0.f, 0.f, 0.f, 0.f, 0.f, 0.f, 0.f};

    const int o0 = g_off[node];
    const int deg = g_off[node + 1] - o0;

    // prefetch meta + gather for edge 0
    int sn;
    float ea0, ea1, ea2;
    if (deg > 0) {
        int eid = g_csr[o0];
        sn = src[eid];
        ea0 = eattr[eid * 3 + 0];
        ea1 = eattr[eid * 3 + 1];
        ea2 = eattr[eid * 3 + 2];
    } else {
        sn = node;
        ea0 = g_loop[node * 3 + 0];
        ea1 = g_loop[node * 3 + 1];
        ea2 = g_loop[node * 3 + 2];
    }
    float xv[8];
    {
        const float4* xp = (const float4*)(xl + (long)sn * HC);
        *(float4*)&xv[0] = xp[b4];
        *(float4*)&xv[4] = xp[b4 + 1];
    }

    for (int i = 0; i <= deg; i++) {
        // current edge values
        float cx[8];
        #pragma unroll
        for (int j = 0; j < 8; j++) cx[j] = xv[j];
        float ce0 = ea0, ce1 = ea1, ce2 = ea2;

        // prefetch next edge (meta + gather) before compute
        if (i < deg) {
            if (i + 1 < deg) {
                int eid = g_csr[o0 + i + 1];
                sn = src[eid];
                ea0 = eattr[eid * 3 + 0];
                ea1 = eattr[eid * 3 + 1];
                ea2 = eattr[eid * 3 + 2];
            } else {
                sn = node;
                ea0 = g_loop[node * 3 + 0];
                ea1 = g_loop[node * 3 + 1];
                ea2 = g_loop[node * 3 + 2];
            }
            const float4* xp = (const float4*)(xl + (long)sn * HC);
            *(float4*)&xv[0] = xp[b4];
            *(float4*)&xv[4] = xp[b4 + 1];
        }

        // attention logit (per head): leakyrelu(xl+xr+ea@We) . att
        float p = 0.f;
        #pragma unroll
        for (int j = 0; j < 8; j++) {
            float t = cx[j] + xrv[j] + ce0 * we0[j] + ce1 * we1[j] + ce2 * we2[j];
            t = (t > 0.f) ? t : 0.2f * t;
            p += t * attv[j];
        }
        // reduce within the 8-lane head group
        p += __shfl_xor_sync(0xffffffffu, p, 1);
        p += __shfl_xor_sync(0xffffffffu, p, 2);
        p += __shfl_xor_sync(0xffffffffu, p, 4);

        // online softmax update
        float nm = fmaxf(m, p);
        float sc = __expf(m - nm);
        float w  = __expf(p - nm);
        s = s * sc + w;
        m = nm;
        #pragma unroll
        for (int j = 0; j < 8; j++) acc[j] = acc[j] * sc + w * cx[j];
    }

    // head mean + bias + relu; cross-head sum via shfl (lanes l, l^8, l^16, l^24)
    float inv = 1.f / s;
    float r[8];
    #pragma unroll
    for (int j = 0; j < 8; j++) {
        float v = acc[j] * inv;
        v += __shfl_xor_sync(0xffffffffu, v, 8);
        v += __shfl_xor_sync(0xffffffffu, v, 16);
        r[j] = v;
    }
    if (lane < 8) {
        float o[8];
        #pragma unroll
        for (int j = 0; j < 8; j++)
            o[j] = fmaxf(0.25f * r[j] + bias[base + j], 0.f);
        float4* op = (float4*)(out + (long)node * CC + base);
        op[0] = make_float4(o[0], o[1], o[2], o[3]);
        op[1] = make_float4(o[4], o[5], o[6], o[7]);
    }
}

// ---------------- launch ----------------
extern "C" void kernel_launch(void* const* d_in, const int* in_sizes, int n_in,
                              void* d_out, int out_size) {
    const float* x          = (const float*)d_in[0];
    const int*   edge_index = (const int*)d_in[1];
    const float* edge_attr  = (const float*)d_in[2];
    const float* Wl0  = (const float*)d_in[3];
    const float* bl0  = (const float*)d_in[4];
    const float* Wr0  = (const float*)d_in[5];
    const float* br0  = (const float*)d_in[6];
    const float* We0  = (const float*)d_in[7];
    const float* att0 = (const float*)d_in[8];
    const float* bias0= (const float*)d_in[9];
    const float* Wl1  = (const float*)d_in[10];
    const float* bl1  = (const float*)d_in[11];
    const float* Wr1  = (const float*)d_in[12];
    const float* br1  = (const float*)d_in[13];
    const float* We1  = (const float*)d_in[14];
    const float* att1 = (const float*)d_in[15];
    const float* bias1= (const float*)d_in[16];
    const float* Wmu  = (const float*)d_in[17];
    const float* bmu  = (const float*)d_in[18];

    const int E = in_sizes[1] / 2;
    const int n = in_sizes[0] / IND;
    const int* src = edge_index;
    const int* dst = edge_index + E;

    void *p_deg, *p_cnt, *p_loop, *p_xl, *p_xr, *p_h1, *p_h2;
    cudaGetSymbolAddress(&p_deg, g_deg);
    cudaGetSymbolAddress(&p_cnt, g_cnt);
    cudaGetSymbolAddress(&p_loop, g_loop);
    cudaGetSymbolAddress(&p_xl, g_xl);
    cudaGetSymbolAddress(&p_xr, g_xr);
    cudaGetSymbolAddress(&p_h1, g_h1);
    cudaGetSymbolAddress(&p_h2, g_h2);

    cudaMemsetAsync(p_deg, 0, (size_t)n * sizeof(int));
    cudaMemsetAsync(p_cnt, 0, (size_t)n * sizeof(int));
    cudaMemsetAsync(p_loop, 0, (size_t)n * EDIM * sizeof(float));

    int eb = (E + 255) / 256;
    int nb = (n + 255) / 256;
    int sb = (n + 1023) / 1024;

    // CSR by destination + self-loop edge attr (graph shared by both layers)
    edge_accum_kernel<<<eb, 256>>>(dst, edge_attr, E);
    scan_block_kernel<<<sb, 1024>>>(n);
    scan_bsum_kernel<<<1, 64>>>(sb);
    scan_add_kernel<<<sb, 1024>>>(n);
    scatter_kernel<<<eb, 256>>>(dst, E);
    loopdiv_kernel<<<nb, 256>>>(n);

    dim3 gdual(4, (n + 127) / 128);
    int aggBlocks = (n * 32 + 255) / 256;

    // ---- layer 0 ----
    gemm_tf32_dual<<<gdual, 256>>>(x, Wl0, Wr0, bl0, br0,
                                   (float*)p_xl, (float*)p_xr, n, IND);
    gat_agg<<<aggBlocks, 256>>>((const float*)p_xl, (const float*)p_xr,
                                src, edge_attr, We0, att0, bias0,
                                (float*)p_h1, n);

    // ---- layer 1 ----
    gemm_tf32_dual<<<gdual, 256>>>((const float*)p_h1, Wl1, Wr1, bl1, br1,
                                   (float*)p_xl, (float*)p_xr, n, CC);
    gat_agg<<<aggBlocks, 256>>>((const float*)p_xl, (const float*)p_xr,
                                src, edge_attr, We1, att1, bias1,
                                (float*)p_h2, n);

    // ---- final projection ----
    dim3 gmu((LAT + 63) / 64, (n + 63) / 64);
    sgemm_bias<<<gmu, 256>>>((const float*)p_h2, Wmu, bmu, (float*)d_out, n, CC, LAT);
}

// round 5
// speedup vs baseline: 2.0842x; 1.0965x over previous
#include <cuda_runtime.h>
#include <math.h>

#define NN 50000
#define EE 800000
#define IND 256
#define HH 4
#define CC 64
#define HC 256   // H*C
#define LAT 32
#define EDIM 3

// ---------------- scratch (device globals; no allocation allowed) ----------------
__device__ int   g_deg[NN];
__device__ int   g_off[NN + 1];
__device__ int   g_cnt[NN];
__device__ int   g_csr[EE];
__device__ int   g_bsum[64];
__device__ float g_loop[NN * EDIM];
__device__ float g_xl[NN * HC];
__device__ float g_xr[NN * HC];
__device__ float g_h1[NN * CC];
__device__ float g_h2[NN * CC];

// ---------------- CSR build ----------------
__global__ void edge_accum_kernel(const int* __restrict__ dst,
                                  const float* __restrict__ ea, int e) {
    int i = blockIdx.x * blockDim.x + threadIdx.x;
    if (i < e) {
        int d = dst[i];
        atomicAdd(&g_deg[d], 1);
        atomicAdd(&g_loop[d * 3 + 0], ea[i * 3 + 0]);
        atomicAdd(&g_loop[d * 3 + 1], ea[i * 3 + 1]);
        atomicAdd(&g_loop[d * 3 + 2], ea[i * 3 + 2]);
    }
}

__global__ void scan_block_kernel(int n) {
    __shared__ int tmp[1024];
    int tid = threadIdx.x;
    int i = blockIdx.x * 1024 + tid;
    int v = (i < n) ? g_deg[i] : 0;
    tmp[tid] = v;
    __syncthreads();
    for (int d = 1; d < 1024; d <<= 1) {
        int t = (tid >= d) ? tmp[tid - d] : 0;
        __syncthreads();
        tmp[tid] += t;
        __syncthreads();
    }
    if (i < n) g_off[i + 1] = tmp[tid];
    if (tid == 1023) g_bsum[blockIdx.x] = tmp[tid];
    if (i == 0) g_off[0] = 0;
}

__global__ void scan_bsum_kernel(int nb) {
    __shared__ int tmp[64];
    int tid = threadIdx.x;
    int v = (tid < nb) ? g_bsum[tid] : 0;
    tmp[tid] = v;
    __syncthreads();
    for (int d = 1; d < 64; d <<= 1) {
        int t = (tid >= d) ? tmp[tid - d] : 0;
        __syncthreads();
        tmp[tid] += t;
        __syncthreads();
    }
    if (tid < nb) g_bsum[tid] = tmp[tid] - v;  // exclusive
}

__global__ void scan_add_kernel(int n) {
    if (blockIdx.x == 0) return;
    int i = blockIdx.x * 1024 + threadIdx.x;
    if (i < n) g_off[i + 1] += g_bsum[blockIdx.x];
}

__global__ void scatter_kernel(const int* __restrict__ dst, int e) {
    int i = blockIdx.x * blockDim.x + threadIdx.x;
    if (i < e) {
        int d = dst[i];
        int p = g_off[d] + atomicAdd(&g_cnt[d], 1);
        g_csr[p] = i;
    }
}

__global__ void loopdiv_kernel(int n) {
    int i = blockIdx.x * blockDim.x + threadIdx.x;
    if (i < n) {
        float inv = 1.0f / (float)max(g_deg[i], 1);
        g_loop[i * 3 + 0] *= inv;
        g_loop[i * 3 + 1] *= inv;
        g_loop[i * 3 + 2] *= inv;
    }
}

// ---------------- TF32 tensor-core GEMM, cp.async double-buffered ----------------
__device__ __forceinline__ unsigned f2tf32(float f) {
    unsigned u;
    asm("cvt.rna.tf32.f32 %0, %1;" : "=r"(u) : "f"(f));
    return u;
}

#define AS_STRIDE 36
#define BS_STRIDE 136
#define AS_STAGE (128 * AS_STRIDE)          // floats per A stage
#define BS_STAGE (32 * BS_STRIDE)           // floats per B stage
#define GEMM_SMEM_BYTES ((2 * AS_STAGE + 2 * BS_STAGE) * 4)

__device__ __forceinline__ void cp16(unsigned saddr, const float* g, unsigned srcsz) {
    asm volatile("cp.async.cg.shared.global [%0], [%1], 16, %2;"
                 :: "r"(saddr), "l"(g), "r"(srcsz));
}

__global__ __launch_bounds__(256) void gemm_tf32_dual(
    const float* __restrict__ A,
    const float* __restrict__ Bl, const float* __restrict__ Br,
    const float* __restrict__ bl, const float* __restrict__ br,
    float* __restrict__ Cl, float* __restrict__ Cr,
    int M, int K)
{
    extern __shared__ float sm[];
    float* Asm = sm;                          // 2 stages of [128][36]
    float* Bsm = sm + 2 * AS_STAGE;           // 2 stages of [32][136]

    const int tid  = threadIdx.x;
    const int lane = tid & 31;
    const int warp = tid >> 5;
    const int g = lane >> 2;
    const int q = lane & 3;

    const int m_warp = (warp & 1) * 64;
    const int n_warp = (warp >> 1) * 32;

    const int row0 = blockIdx.y * 128;
    const int col0 = blockIdx.x * 128;
    const int half = (col0 >= 256);
    const float* Bp = half ? Br : Bl;
    const float* biasp = half ? br : bl;
    float* Cp = half ? Cr : Cl;
    const int bcol0 = col0 - half * 256;

    // per-thread cp.async slots (4 for A, 4 for B per stage)
    const int ar = tid >> 1;                  // 0..127 (A row), 2 threads per row
    const int ac4 = (tid & 1) * 4;            // c4 = 0 or 4 -> two halves handled by it loop
    const int brow = tid >> 3;                // 0..31 (B row)
    const int bc4 = (tid & 7) * 4;            // 0..28

    const unsigned asm_base = (unsigned)__cvta_generic_to_shared(Asm);
    const unsigned bsm_base = (unsigned)__cvta_generic_to_shared(Bsm);

    float acc[4][4][4] = {};
    const int nk = K >> 5;

    // ---- stage-load helper (macro-ish lambda) ----
    auto load_stage = [&](int stg, int k0) {
        // A: 128 rows x 32 cols = 1024 x 16B; each thread does 4
        const int garow = row0 + ar;
        const int carow = (garow < M) ? garow : (M - 1);
        const unsigned asz = (garow < M) ? 16u : 0u;
        const float* gA = A + (long)carow * K + k0;
        unsigned sA = asm_base + (stg * AS_STAGE + ar * AS_STRIDE) * 4;
        #pragma unroll
        for (int h2 = 0; h2 < 2; h2++) {
            int c4 = ac4 + h2 * 16;           // wait: need cols 0..31 => c4 in {0,4,16,20}? fix below
            (void)c4;
        }
        // simpler: 4 chunks at c = ac4*? -> cover 32 floats with 2 threads: thread half 0 covers 0..15, half 1 covers 16..31
        {
            int cbase = (tid & 1) * 16;
            cp16(sA + (cbase + 0) * 4, gA + cbase + 0, asz);
            cp16(sA + (cbase + 4) * 4, gA + cbase + 4, asz);
            cp16(sA + (cbase + 8) * 4, gA + cbase + 8, asz);
            cp16(sA + (cbase + 12) * 4, gA + cbase + 12, asz);
        }
        // B: 32 rows x 128 cols = 1024 x 16B; each thread does 4 (rows brow, brow+... )
        {
            const float* gB = Bp + (long)(k0 + brow) * 256 + bcol0 + bc4;
            unsigned sB = bsm_base + (stg * BS_STAGE + brow * BS_STRIDE + bc4) * 4;
            cp16(sB, gB, 16u);
            cp16(sB + 32 * 4, gB + 32, 16u);
            cp16(sB + 64 * 4, gB + 64, 16u);
            cp16(sB + 96 * 4, gB + 96, 16u);
        }
    };

    load_stage(0, 0);
    asm volatile("cp.async.commit_group;");

    for (int kt = 0; kt < nk; kt++) {
        if (kt + 1 < nk) load_stage((kt + 1) & 1, (kt + 1) * 32);
        asm volatile("cp.async.commit_group;");
        asm volatile("cp.async.wait_group 1;");
        __syncthreads();

        const float* As = Asm + (kt & 1) * AS_STAGE;
        const float* Bs = Bsm + (kt & 1) * BS_STAGE;

        #pragma unroll
        for (int kk = 0; kk < 32; kk += 8) {
            unsigned a[4][4], b[4][2];
            #pragma unroll
            for (int i = 0; i < 4; i++) {
                int r = m_warp + i * 16 + g;
                a[i][0] = f2tf32(As[r * AS_STRIDE + kk + q]);
                a[i][1] = f2tf32(As[(r + 8) * AS_STRIDE + kk + q]);
                a[i][2] = f2tf32(As[r * AS_STRIDE + kk + q + 4]);
                a[i][3] = f2tf32(As[(r + 8) * AS_STRIDE + kk + q + 4]);
            }
            #pragma unroll
            for (int j = 0; j < 4; j++) {
                int c = n_warp + j * 8 + g;
                b[j][0] = f2tf32(Bs[(kk + q) * BS_STRIDE + c]);
                b[j][1] = f2tf32(Bs[(kk + q + 4) * BS_STRIDE + c]);
            }
            #pragma unroll
            for (int i = 0; i < 4; i++)
                #pragma unroll
                for (int j = 0; j < 4; j++) {
                    asm volatile(
                        "mma.sync.aligned.m16n8k8.row.col.f32.tf32.tf32.f32 "
                        "{%0,%1,%2,%3}, {%4,%5,%6,%7}, {%8,%9}, {%0,%1,%2,%3};"
                        : "+f"(acc[i][j][0]), "+f"(acc[i][j][1]),
                          "+f"(acc[i][j][2]), "+f"(acc[i][j][3])
                        : "r"(a[i][0]), "r"(a[i][1]), "r"(a[i][2]), "r"(a[i][3]),
                          "r"(b[j][0]), "r"(b[j][1]));
                }
        }
        __syncthreads();
    }

    #pragma unroll
    for (int i = 0; i < 4; i++) {
        int r0 = row0 + m_warp + i * 16 + g;
        #pragma unroll
        for (int j = 0; j < 4; j++) {
            int cl = bcol0 + n_warp + j * 8 + 2 * q;
            float b0 = biasp[cl], b1 = biasp[cl + 1];
            if (r0 < M) {
                Cp[(long)r0 * 256 + cl]     = acc[i][j][0] + b0;
                Cp[(long)r0 * 256 + cl + 1] = acc[i][j][1] + b1;
            }
            if (r0 + 8 < M) {
                Cp[(long)(r0 + 8) * 256 + cl]     = acc[i][j][2] + b0;
                Cp[(long)(r0 + 8) * 256 + cl + 1] = acc[i][j][3] + b1;
            }
        }
    }
}

// ---------------- fp32 tiled SGEMM (final projection only) ----------------
__global__ void sgemm_bias(const float* __restrict__ A, const float* __restrict__ B,
                           const float* __restrict__ bias, float* __restrict__ C,
                           int M, int K, int Nc) {
    __shared__ float As[16][64];
    __shared__ float Bs[16][64 + 4];
    int tid = threadIdx.x;
    int tx = tid & 15, ty = tid >> 4;
    int row0 = blockIdx.y * 64, col0 = blockIdx.x * 64;
    float acc[4][4] = {};
    for (int k0 = 0; k0 < K; k0 += 16) {
        #pragma unroll
        for (int i = tid; i < 64 * 16; i += 256) {
            int m = i >> 4, k = i & 15;
            int r = row0 + m;
            As[k][m] = (r < M) ? A[(long)r * K + k0 + k] : 0.0f;
        }
        #pragma unroll
        for (int i = tid; i < 16 * 64; i += 256) {
            int k = i >> 6, c = i & 63;
            int cc = col0 + c;
            Bs[k][c] = (cc < Nc) ? B[(long)(k0 + k) * Nc + cc] : 0.0f;
        }
        __syncthreads();
        #pragma unroll
        for (int k = 0; k < 16; k++) {
            float a[4], b[4];
            #pragma unroll
            for (int i = 0; i < 4; i++) a[i] = As[k][ty * 4 + i];
            #pragma unroll
            for (int j = 0; j < 4; j++) b[j] = Bs[k][tx * 4 + j];
            #pragma unroll
            for (int i = 0; i < 4; i++)
                #pragma unroll
                for (int j = 0; j < 4; j++)
                    acc[i][j] += a[i] * b[j];
        }
        __syncthreads();
    }
    #pragma unroll
    for (int i = 0; i < 4; i++) {
        int r = row0 + ty * 4 + i;
        if (r >= M) continue;
        #pragma unroll
        for (int j = 0; j < 4; j++) {
            int c = col0 + tx * 4 + j;
            if (c < Nc) C[(long)r * Nc + c] = acc[i][j] + bias[c];
        }
    }
}

// ---------------- fused GATv2 attention + aggregation ----------------
// One warp per dst node; lane l owns 8 contiguous channels of head l>>3.
// Pipeline: edge meta prefetched at distance 2, xl-row gather at distance 1.
__global__ void gat_agg(const float* __restrict__ xl, const float* __restrict__ xr,
                        const int* __restrict__ src, const float* __restrict__ eattr,
                        const float* __restrict__ We, const float* __restrict__ att,
                        const float* __restrict__ bias, float* __restrict__ out,
                        int n) {
    int warp = (blockIdx.x * blockDim.x + threadIdx.x) >> 5;
    int lane = threadIdx.x & 31;
    if (warp >= n) return;
    const int node = warp;
    const int base = ((lane >> 3) << 6) | ((lane & 7) << 3);
    const int b4 = base >> 2;

    float we0[8], we1[8], we2[8], attv[8], xrv[8];
    {
        const float4* We4 = (const float4*)We;
        const float4* at4 = (const float4*)att;
        const float4* xr4 = (const float4*)(xr + (long)node * HC);
        *(float4*)&we0[0] = We4[b4];        *(float4*)&we0[4] = We4[b4 + 1];
        *(float4*)&we1[0] = We4[64 + b4];   *(float4*)&we1[4] = We4[64 + b4 + 1];
        *(float4*)&we2[0] = We4[128 + b4];  *(float4*)&we2[4] = We4[128 + b4 + 1];
        *(float4*)&attv[0] = at4[b4];       *(float4*)&attv[4] = at4[b4 + 1];
        *(float4*)&xrv[0] = xr4[b4];        *(float4*)&xrv[4] = xr4[b4 + 1];
    }

    float m = -1e30f, s = 0.f;
    float acc[8] = {0.f, 0.f, 0.f, 0.f, 0.f, 0.f, 0.f, 0.f};

    const int o0 = g_off[node];
    const int deg = g_off[node + 1] - o0;

    // meta ring (distance 2)
    int   sn0, sn1;
    float e00, e01, e02, e10, e11, e12;

    // fetch_meta(0)
    if (deg > 0) {
        int eid = g_csr[o0];
        sn0 = src[eid];
        e00 = eattr[eid * 3 + 0]; e01 = eattr[eid * 3 + 1]; e02 = eattr[eid * 3 + 2];
    } else {
        sn0 = node;
        e00 = g_loop[node * 3 + 0]; e01 = g_loop[node * 3 + 1]; e02 = g_loop[node * 3 + 2];
    }
    // fetch_meta(1)
    if (deg >= 1) {
        if (1 < deg) {
            int eid = g_csr[o0 + 1];
            sn1 = src[eid];
            e10 = eattr[eid * 3 + 0]; e11 = eattr[eid * 3 + 1]; e12 = eattr[eid * 3 + 2];
        } else {
            sn1 = node;
            e10 = g_loop[node * 3 + 0]; e11 = g_loop[node * 3 + 1]; e12 = g_loop[node * 3 + 2];
        }
    } else { sn1 = sn0; e10 = e00; e11 = e01; e12 = e02; }

    // gather for edge 0
    float xv[8];
    {
        const float4* xp = (const float4*)(xl + (long)sn0 * HC);
        *(float4*)&xv[0] = xp[b4];
        *(float4*)&xv[4] = xp[b4 + 1];
    }

    for (int i = 0; i <= deg; i++) {
        // current values
        float cx[8];
        #pragma unroll
        for (int j = 0; j < 8; j++) cx[j] = xv[j];
        const float ce0 = e00, ce1 = e01, ce2 = e02;

        // rotate meta ring; fetch meta for i+2
        sn0 = sn1; e00 = e10; e01 = e11; e02 = e12;
        if (i + 2 <= deg) {
            if (i + 2 < deg) {
                int eid = g_csr[o0 + i + 2];
                sn1 = src[eid];
                e10 = eattr[eid * 3 + 0]; e11 = eattr[eid * 3 + 1]; e12 = eattr[eid * 3 + 2];
            } else {
                sn1 = node;
                e10 = g_loop[node * 3 + 0]; e11 = g_loop[node * 3 + 1]; e12 = g_loop[node * 3 + 2];
            }
        }
        // gather for edge i+1 (address already resolved)
        if (i + 1 <= deg) {
            const float4* xp = (const float4*)(xl + (long)sn0 * HC);
            *(float4*)&xv[0] = xp[b4];
            *(float4*)&xv[4] = xp[b4 + 1];
        }

        // attention logit
        float p = 0.f;
        #pragma unroll
        for (int j = 0; j < 8; j++) {
            float t = cx[j] + xrv[j] + ce0 * we0[j] + ce1 * we1[j] + ce2 * we2[j];
            t = (t > 0.f) ? t : 0.2f * t;
            p += t * attv[j];
        }
        p += __shfl_xor_sync(0xffffffffu, p, 1);
        p += __shfl_xor_sync(0xffffffffu, p, 2);
        p += __shfl_xor_sync(0xffffffffu, p, 4);

        // online softmax
        float nm = fmaxf(m, p);
        float sc = __expf(m - nm);
        float w  = __expf(p - nm);
        s = s * sc + w;
        m = nm;
        #pragma unroll
        for (int j = 0; j < 8; j++) acc[j] = acc[j] * sc + w * cx[j];
    }

    float inv = 1.f / s;
    float r[8];
    #pragma unroll
    for (int j = 0; j < 8; j++) {
        float v = acc[j] * inv;
        v += __shfl_xor_sync(0xffffffffu, v, 8);
        v += __shfl_xor_sync(0xffffffffu, v, 16);
        r[j] = v;
    }
    if (lane < 8) {
        float o[8];
        #pragma unroll
        for (int j = 0; j < 8; j++)
            o[j] = fmaxf(0.25f * r[j] + bias[base + j], 0.f);
        float4* op = (float4*)(out + (long)node * CC + base);
        op[0] = make_float4(o[0], o[1], o[2], o[3]);
        op[1] = make_float4(o[4], o[5], o[6], o[7]);
    }
}

// ---------------- launch ----------------
extern "C" void kernel_launch(void* const* d_in, const int* in_sizes, int n_in,
                              void* d_out, int out_size) {
    const float* x          = (const float*)d_in[0];
    const int*   edge_index = (const int*)d_in[1];
    const float* edge_attr  = (const float*)d_in[2];
    const float* Wl0  = (const float*)d_in[3];
    const float* bl0  = (const float*)d_in[4];
    const float* Wr0  = (const float*)d_in[5];
    const float* br0  = (const float*)d_in[6];
    const float* We0  = (const float*)d_in[7];
    const float* att0 = (const float*)d_in[8];
    const float* bias0= (const float*)d_in[9];
    const float* Wl1  = (const float*)d_in[10];
    const float* bl1  = (const float*)d_in[11];
    const float* Wr1  = (const float*)d_in[12];
    const float* br1  = (const float*)d_in[13];
    const float* We1  = (const float*)d_in[14];
    const float* att1 = (const float*)d_in[15];
    const float* bias1= (const float*)d_in[16];
    const float* Wmu  = (const float*)d_in[17];
    const float* bmu  = (const float*)d_in[18];

    const int E = in_sizes[1] / 2;
    const int n = in_sizes[0] / IND;
    const int* src = edge_index;
    const int* dst = edge_index + E;

    void *p_deg, *p_cnt, *p_loop, *p_xl, *p_xr, *p_h1, *p_h2;
    cudaGetSymbolAddress(&p_deg, g_deg);
    cudaGetSymbolAddress(&p_cnt, g_cnt);
    cudaGetSymbolAddress(&p_loop, g_loop);
    cudaGetSymbolAddress(&p_xl, g_xl);
    cudaGetSymbolAddress(&p_xr, g_xr);
    cudaGetSymbolAddress(&p_h1, g_h1);
    cudaGetSymbolAddress(&p_h2, g_h2);

    cudaMemsetAsync(p_deg, 0, (size_t)n * sizeof(int));
    cudaMemsetAsync(p_cnt, 0, (size_t)n * sizeof(int));
    cudaMemsetAsync(p_loop, 0, (size_t)n * EDIM * sizeof(float));

    cudaFuncSetAttribute(gemm_tf32_dual,
                         cudaFuncAttributeMaxDynamicSharedMemorySize,
                         GEMM_SMEM_BYTES);

    int eb = (E + 255) / 256;
    int nb = (n + 255) / 256;
    int sb = (n + 1023) / 1024;

    edge_accum_kernel<<<eb, 256>>>(dst, edge_attr, E);
    scan_block_kernel<<<sb, 1024>>>(n);
    scan_bsum_kernel<<<1, 64>>>(sb);
    scan_add_kernel<<<sb, 1024>>>(n);
    scatter_kernel<<<eb, 256>>>(dst, E);
    loopdiv_kernel<<<nb, 256>>>(n);

    dim3 gdual(4, (n + 127) / 128);
    int aggBlocks = (n * 32 + 255) / 256;

    // ---- layer 0 ----
    gemm_tf32_dual<<<gdual, 256, GEMM_SMEM_BYTES>>>(x, Wl0, Wr0, bl0, br0,
                                   (float*)p_xl, (float*)p_xr, n, IND);
    gat_agg<<<aggBlocks, 256>>>((const float*)p_xl, (const float*)p_xr,
                                src, edge_attr, We0, att0, bias0,
                                (float*)p_h1, n);

    // ---- layer 1 ----
    gemm_tf32_dual<<<gdual, 256, GEMM_SMEM_BYTES>>>((const float*)p_h1, Wl1, Wr1, bl1, br1,
                                   (float*)p_xl, (float*)p_xr, n, CC);
    gat_agg<<<aggBlocks, 256>>>((const float*)p_xl, (const float*)p_xr,
                                src, edge_attr, We1, att1, bias1,
                                (float*)p_h2, n);

    // ---- final projection ----
    dim3 gmu((LAT + 63) / 64, (n + 63) / 64);
    sgemm_bias<<<gmu, 256>>>((const float*)p_h2, Wmu, bmu, (float*)d_out, n, CC, LAT);
}

// round 6
// speedup vs baseline: 2.6679x; 1.2801x over previous
#include <cuda_runtime.h>
#include <math.h>

#define NN 50000
#define EE 800000
#define IND 256
#define HH 4
#define CC 64
#define HC 256   // H*C
#define LAT 32
#define EDIM 3

// ---------------- scratch (device globals; no allocation allowed) ----------------
__device__ int   g_deg[NN];
__device__ int   g_off[NN + 1];
__device__ int   g_cnt[NN];
__device__ int   g_csr[EE];
__device__ int   g_bsum[64];
__device__ float g_loop[NN * EDIM];
__device__ float g_xl[NN * HC];
__device__ float g_xr[NN * HC];
__device__ float g_h1[NN * CC];
__device__ float g_h2[NN * CC];

// ---------------- CSR build ----------------
__global__ void edge_accum_kernel(const int* __restrict__ dst,
                                  const float* __restrict__ ea, int e) {
    int i = blockIdx.x * blockDim.x + threadIdx.x;
    if (i < e) {
        int d = dst[i];
        atomicAdd(&g_deg[d], 1);
        atomicAdd(&g_loop[d * 3 + 0], ea[i * 3 + 0]);
        atomicAdd(&g_loop[d * 3 + 1], ea[i * 3 + 1]);
        atomicAdd(&g_loop[d * 3 + 2], ea[i * 3 + 2]);
    }
}

__global__ void scan_block_kernel(int n) {
    __shared__ int tmp[1024];
    int tid = threadIdx.x;
    int i = blockIdx.x * 1024 + tid;
    int v = (i < n) ? g_deg[i] : 0;
    tmp[tid] = v;
    __syncthreads();
    for (int d = 1; d < 1024; d <<= 1) {
        int t = (tid >= d) ? tmp[tid - d] : 0;
        __syncthreads();
        tmp[tid] += t;
        __syncthreads();
    }
    if (i < n) g_off[i + 1] = tmp[tid];
    if (tid == 1023) g_bsum[blockIdx.x] = tmp[tid];
    if (i == 0) g_off[0] = 0;
}

__global__ void scan_bsum_kernel(int nb) {
    __shared__ int tmp[64];
    int tid = threadIdx.x;
    int v = (tid < nb) ? g_bsum[tid] : 0;
    tmp[tid] = v;
    __syncthreads();
    for (int d = 1; d < 64; d <<= 1) {
        int t = (tid >= d) ? tmp[tid - d] : 0;
        __syncthreads();
        tmp[tid] += t;
        __syncthreads();
    }
    if (tid < nb) g_bsum[tid] = tmp[tid] - v;  // exclusive
}

// adds block prefix AND finalizes loop_attr mean (folded loopdiv)
__global__ void scan_add_kernel(int n) {
    int i = blockIdx.x * 1024 + threadIdx.x;
    if (i < n) {
        if (blockIdx.x > 0) g_off[i + 1] += g_bsum[blockIdx.x];
        float inv = 1.0f / (float)max(g_deg[i], 1);
        g_loop[i * 3 + 0] *= inv;
        g_loop[i * 3 + 1] *= inv;
        g_loop[i * 3 + 2] *= inv;
    }
}

__global__ void scatter_kernel(const int* __restrict__ dst, int e) {
    int i = blockIdx.x * blockDim.x + threadIdx.x;
    if (i < e) {
        int d = dst[i];
        int p = g_off[d] + atomicAdd(&g_cnt[d], 1);
        g_csr[p] = i;
    }
}

// ---------------- TF32 tensor-core GEMM, cp.async double-buffered ----------------
__device__ __forceinline__ unsigned f2tf32(float f) {
    unsigned u;
    asm("cvt.rna.tf32.f32 %0, %1;" : "=r"(u) : "f"(f));
    return u;
}

#define AS_STRIDE 36
#define BS_STRIDE 136
#define AS_STAGE (128 * AS_STRIDE)
#define BS_STAGE (32 * BS_STRIDE)
#define GEMM_SMEM_BYTES ((2 * AS_STAGE + 2 * BS_STAGE) * 4)

__device__ __forceinline__ void cp16(unsigned saddr, const float* g, unsigned srcsz) {
    asm volatile("cp.async.cg.shared.global [%0], [%1], 16, %2;"
                 :: "r"(saddr), "l"(g), "r"(srcsz));
}

__global__ __launch_bounds__(256) void gemm_tf32_dual(
    const float* __restrict__ A,
    const float* __restrict__ Bl, const float* __restrict__ Br,
    const float* __restrict__ bl, const float* __restrict__ br,
    float* __restrict__ Cl, float* __restrict__ Cr,
    int M, int K)
{
    extern __shared__ float sm[];
    float* Asm = sm;
    float* Bsm = sm + 2 * AS_STAGE;

    const int tid  = threadIdx.x;
    const int lane = tid & 31;
    const int warp = tid >> 5;
    const int g = lane >> 2;
    const int q = lane & 3;

    const int m_warp = (warp & 1) * 64;
    const int n_warp = (warp >> 1) * 32;

    const int row0 = blockIdx.y * 128;
    const int col0 = blockIdx.x * 128;
    const int half = (col0 >= 256);
    const float* Bp = half ? Br : Bl;
    const float* biasp = half ? br : bl;
    float* Cp = half ? Cr : Cl;
    const int bcol0 = col0 - half * 256;

    const int ar = tid >> 1;
    const int brow = tid >> 3;
    const int bc4 = (tid & 7) * 4;

    const unsigned asm_base = (unsigned)__cvta_generic_to_shared(Asm);
    const unsigned bsm_base = (unsigned)__cvta_generic_to_shared(Bsm);

    float acc[4][4][4] = {};
    const int nk = K >> 5;

    auto load_stage = [&](int stg, int k0) {
        const int garow = row0 + ar;
        const int carow = (garow < M) ? garow : (M - 1);
        const unsigned asz = (garow < M) ? 16u : 0u;
        const float* gA = A + (long)carow * K + k0;
        unsigned sA = asm_base + (stg * AS_STAGE + ar * AS_STRIDE) * 4;
        int cbase = (tid & 1) * 16;
        cp16(sA + (cbase + 0) * 4, gA + cbase + 0, asz);
        cp16(sA + (cbase + 4) * 4, gA + cbase + 4, asz);
        cp16(sA + (cbase + 8) * 4, gA + cbase + 8, asz);
        cp16(sA + (cbase + 12) * 4, gA + cbase + 12, asz);
        const float* gB = Bp + (long)(k0 + brow) * 256 + bcol0 + bc4;
        unsigned sB = bsm_base + (stg * BS_STAGE + brow * BS_STRIDE + bc4) * 4;
        cp16(sB, gB, 16u);
        cp16(sB + 32 * 4, gB + 32, 16u);
        cp16(sB + 64 * 4, gB + 64, 16u);
        cp16(sB + 96 * 4, gB + 96, 16u);
    };

    load_stage(0, 0);
    asm volatile("cp.async.commit_group;");

    for (int kt = 0; kt < nk; kt++) {
        if (kt + 1 < nk) load_stage((kt + 1) & 1, (kt + 1) * 32);
        asm volatile("cp.async.commit_group;");
        asm volatile("cp.async.wait_group 1;");
        __syncthreads();

        const float* As = Asm + (kt & 1) * AS_STAGE;
        const float* Bs = Bsm + (kt & 1) * BS_STAGE;

        #pragma unroll
        for (int kk = 0; kk < 32; kk += 8) {
            unsigned a[4][4], b[4][2];
            #pragma unroll
            for (int i = 0; i < 4; i++) {
                int r = m_warp + i * 16 + g;
                a[i][0] = f2tf32(As[r * AS_STRIDE + kk + q]);
                a[i][1] = f2tf32(As[(r + 8) * AS_STRIDE + kk + q]);
                a[i][2] = f2tf32(As[r * AS_STRIDE + kk + q + 4]);
                a[i][3] = f2tf32(As[(r + 8) * AS_STRIDE + kk + q + 4]);
            }
            #pragma unroll
            for (int j = 0; j < 4; j++) {
                int c = n_warp + j * 8 + g;
                b[j][0] = f2tf32(Bs[(kk + q) * BS_STRIDE + c]);
                b[j][1] = f2tf32(Bs[(kk + q + 4) * BS_STRIDE + c]);
            }
            #pragma unroll
            for (int i = 0; i < 4; i++)
                #pragma unroll
                for (int j = 0; j < 4; j++) {
                    asm volatile(
                        "mma.sync.aligned.m16n8k8.row.col.f32.tf32.tf32.f32 "
                        "{%0,%1,%2,%3}, {%4,%5,%6,%7}, {%8,%9}, {%0,%1,%2,%3};"
                        : "+f"(acc[i][j][0]), "+f"(acc[i][j][1]),
                          "+f"(acc[i][j][2]), "+f"(acc[i][j][3])
                        : "r"(a[i][0]), "r"(a[i][1]), "r"(a[i][2]), "r"(a[i][3]),
                          "r"(b[j][0]), "r"(b[j][1]));
                }
        }
        __syncthreads();
    }

    #pragma unroll
    for (int i = 0; i < 4; i++) {
        int r0 = row0 + m_warp + i * 16 + g;
        #pragma unroll
        for (int j = 0; j < 4; j++) {
            int cl = bcol0 + n_warp + j * 8 + 2 * q;
            float b0 = biasp[cl], b1 = biasp[cl + 1];
            if (r0 < M) {
                Cp[(long)r0 * 256 + cl]     = acc[i][j][0] + b0;
                Cp[(long)r0 * 256 + cl + 1] = acc[i][j][1] + b1;
            }
            if (r0 + 8 < M) {
                Cp[(long)(r0 + 8) * 256 + cl]     = acc[i][j][2] + b0;
                Cp[(long)(r0 + 8) * 256 + cl + 1] = acc[i][j][3] + b1;
            }
        }
    }
}

// ---------------- fp32 tiled SGEMM (final projection only) ----------------
__global__ void sgemm_bias(const float* __restrict__ A, const float* __restrict__ B,
                           const float* __restrict__ bias, float* __restrict__ C,
                           int M, int K, int Nc) {
    __shared__ float As[16][64];
    __shared__ float Bs[16][64 + 4];
    int tid = threadIdx.x;
    int tx = tid & 15, ty = tid >> 4;
    int row0 = blockIdx.y * 64, col0 = blockIdx.x * 64;
    float acc[4][4] = {};
    for (int k0 = 0; k0 < K; k0 += 16) {
        #pragma unroll
        for (int i = tid; i < 64 * 16; i += 256) {
            int m = i >> 4, k = i & 15;
            int r = row0 + m;
            As[k][m] = (r < M) ? A[(long)r * K + k0 + k] : 0.0f;
        }
        #pragma unroll
        for (int i = tid; i < 16 * 64; i += 256) {
            int k = i >> 6, c = i & 63;
            int cc = col0 + c;
            Bs[k][c] = (cc < Nc) ? B[(long)(k0 + k) * Nc + cc] : 0.0f;
        }
        __syncthreads();
        #pragma unroll
        for (int k = 0; k < 16; k++) {
            float a[4], b[4];
            #pragma unroll
            for (int i = 0; i < 4; i++) a[i] = As[k][ty * 4 + i];
            #pragma unroll
            for (int j = 0; j < 4; j++) b[j] = Bs[k][tx * 4 + j];
            #pragma unroll
            for (int i = 0; i < 4; i++)
                #pragma unroll
                for (int j = 0; j < 4; j++)
                    acc[i][j] += a[i] * b[j];
        }
        __syncthreads();
    }
    #pragma unroll
    for (int i = 0; i < 4; i++) {
        int r = row0 + ty * 4 + i;
        if (r >= M) continue;
        #pragma unroll
        for (int j = 0; j < 4; j++) {
            int c = col0 + tx * 4 + j;
            if (c < Nc) C[(long)r * Nc + c] = acc[i][j] + bias[c];
        }
    }
}

// ---------------- fused GATv2 attention + aggregation ----------------
// One warp per dst node; lane l owns 8 contiguous channels of head l>>3.
// Two edges per iteration into independent online-softmax states (A/B),
// merged at the end. Meta queue depth = 2 pairs so gathers never wait on
// freshly-loaded indices.
__global__ __launch_bounds__(256) void gat_agg(
        const float* __restrict__ xl, const float* __restrict__ xr,
        const int* __restrict__ src, const float* __restrict__ eattr,
        const float* __restrict__ We, const float* __restrict__ att,
        const float* __restrict__ bias, float* __restrict__ out,
        int n) {
    int warp = (blockIdx.x * blockDim.x + threadIdx.x) >> 5;
    int lane = threadIdx.x & 31;
    if (warp >= n) return;
    const int node = warp;
    const int base = ((lane >> 3) << 6) | ((lane & 7) << 3);
    const int b4 = base >> 2;

    float we0[8], we1[8], we2[8], attv[8], xrv[8];
    {
        const float4* We4 = (const float4*)We;
        const float4* at4 = (const float4*)att;
        const float4* xr4 = (const float4*)(xr + (long)node * HC);
        *(float4*)&we0[0] = We4[b4];        *(float4*)&we0[4] = We4[b4 + 1];
        *(float4*)&we1[0] = We4[64 + b4];   *(float4*)&we1[4] = We4[64 + b4 + 1];
        *(float4*)&we2[0] = We4[128 + b4];  *(float4*)&we2[4] = We4[128 + b4 + 1];
        *(float4*)&attv[0] = at4[b4];       *(float4*)&attv[4] = at4[b4 + 1];
        *(float4*)&xrv[0] = xr4[b4];        *(float4*)&xrv[4] = xr4[b4 + 1];
    }

    const int o0 = g_off[node];
    const int deg = g_off[node + 1] - o0;

    auto fetch = [&](int pos, int& sn, float& e0, float& e1, float& e2) {
        if (pos < deg) {
            int eid = __ldg(&g_csr[o0 + pos]);
            sn = __ldg(&src[eid]);
            e0 = __ldg(&eattr[eid * 3 + 0]);
            e1 = __ldg(&eattr[eid * 3 + 1]);
            e2 = __ldg(&eattr[eid * 3 + 2]);
        } else { sn = node; e0 = 0.f; e1 = 0.f; e2 = 0.f; }
    };

    // ---- state A seeded with the self-loop, state B empty ----
    float accA[8], accB[8];
    float mA, sA, mB = -1e30f, sB = 0.f;
    {
        float xvS[8];
        const float4* xp = (const float4*)(xl + (long)node * HC);
        *(float4*)&xvS[0] = xp[b4];
        *(float4*)&xvS[4] = xp[b4 + 1];
        float l0 = g_loop[node * 3 + 0], l1 = g_loop[node * 3 + 1], l2 = g_loop[node * 3 + 2];
        float p = 0.f;
        #pragma unroll
        for (int j = 0; j < 8; j++) {
            float t = xvS[j] + xrv[j] + l0 * we0[j] + l1 * we1[j] + l2 * we2[j];
            t = (t > 0.f) ? t : 0.2f * t;
            p += t * attv[j];
        }
        p += __shfl_xor_sync(0xffffffffu, p, 1);
        p += __shfl_xor_sync(0xffffffffu, p, 2);
        p += __shfl_xor_sync(0xffffffffu, p, 4);
        mA = p; sA = 1.f;
        #pragma unroll
        for (int j = 0; j < 8; j++) { accA[j] = xvS[j]; accB[j] = 0.f; }
    }

    // ---- meta queue: pair 0 (current) + pair 1 (next) ----
    int snA0, snB0, snA1, snB1;
    float a00, a01, a02, b00, b01, b02;
    float a10, a11, a12, b10, b11, b12;
    fetch(0, snA0, a00, a01, a02);
    fetch(1, snB0, b00, b01, b02);
    float xvA[8], xvB[8];
    {
        const float4* xp = (const float4*)(xl + (long)snA0 * HC);
        *(float4*)&xvA[0] = xp[b4]; *(float4*)&xvA[4] = xp[b4 + 1];
    }
    {
        const float4* xp = (const float4*)(xl + (long)snB0 * HC);
        *(float4*)&xvB[0] = xp[b4]; *(float4*)&xvB[4] = xp[b4 + 1];
    }
    fetch(2, snA1, a10, a11, a12);
    fetch(3, snB1, b10, b11, b12);

    for (int i = 0; i < deg; i += 2) {
        // snapshot current pair
        float cxA[8], cxB[8];
        #pragma unroll
        for (int j = 0; j < 8; j++) { cxA[j] = xvA[j]; cxB[j] = xvB[j]; }
        const float cA0 = a00, cA1 = a01, cA2 = a02;
        const float cB0 = b00, cB1 = b01, cB2 = b02;
        const bool vB = (i + 1 < deg);

        // issue gathers for next pair (meta already resolved last iteration)
        if (i + 2 < deg) {
            const float4* xp = (const float4*)(xl + (long)snA1 * HC);
            *(float4*)&xvA[0] = xp[b4]; *(float4*)&xvA[4] = xp[b4 + 1];
        }
        if (i + 3 < deg) {
            const float4* xp = (const float4*)(xl + (long)snB1 * HC);
            *(float4*)&xvB[0] = xp[b4]; *(float4*)&xvB[4] = xp[b4 + 1];
        }
        // rotate meta queue; fetch pair+2
        snA0 = snA1; a00 = a10; a01 = a11; a02 = a12;
        snB0 = snB1; b00 = b10; b01 = b11; b02 = b12;
        fetch(i + 4, snA1, a10, a11, a12);
        fetch(i + 5, snB1, b10, b11, b12);

        // attention logits for both edges
        float pA = 0.f, pB = 0.f;
        #pragma unroll
        for (int j = 0; j < 8; j++) {
            float tA = cxA[j] + xrv[j] + cA0 * we0[j] + cA1 * we1[j] + cA2 * we2[j];
            tA = (tA > 0.f) ? tA : 0.2f * tA;
            pA += tA * attv[j];
            float tB = cxB[j] + xrv[j] + cB0 * we0[j] + cB1 * we1[j] + cB2 * we2[j];
            tB = (tB > 0.f) ? tB : 0.2f * tB;
            pB += tB * attv[j];
        }
        pA += __shfl_xor_sync(0xffffffffu, pA, 1);
        pB += __shfl_xor_sync(0xffffffffu, pB, 1);
        pA += __shfl_xor_sync(0xffffffffu, pA, 2);
        pB += __shfl_xor_sync(0xffffffffu, pB, 2);
        pA += __shfl_xor_sync(0xffffffffu, pA, 4);
        pB += __shfl_xor_sync(0xffffffffu, pB, 4);
        if (!vB) pB = -1e30f;   // sentinel: keeps nmB == mB

        // online softmax updates (independent states)
        float nmA = fmaxf(mA, pA), nmB = fmaxf(mB, pB);
        float scA = __expf(mA - nmA), wA = __expf(pA - nmA);
        float scB = __expf(mB - nmB), wB = __expf(pB - nmB);
        if (!vB) wB = 0.f;      // required when mB is still -1e30
        sA = sA * scA + wA; mA = nmA;
        sB = sB * scB + wB; mB = nmB;
        #pragma unroll
        for (int j = 0; j < 8; j++) {
            accA[j] = accA[j] * scA + wA * cxA[j];
            accB[j] = accB[j] * scB + wB * cxB[j];
        }
    }

    // ---- merge states, head mean, bias, relu ----
    float nm = fmaxf(mA, mB);
    float fA = __expf(mA - nm), fB = __expf(mB - nm);
    float inv = 1.f / (sA * fA + sB * fB);
    float r[8];
    #pragma unroll
    for (int j = 0; j < 8; j++) {
        float v = (accA[j] * fA + accB[j] * fB) * inv;
        v += __shfl_xor_sync(0xffffffffu, v, 8);
        v += __shfl_xor_sync(0xffffffffu, v, 16);
        r[j] = v;
    }
    if (lane < 8) {
        float o[8];
        #pragma unroll
        for (int j = 0; j < 8; j++)
            o[j] = fmaxf(0.25f * r[j] + bias[base + j], 0.f);
        float4* op = (float4*)(out + (long)node * CC + base);
        op[0] = make_float4(o[0], o[1], o[2], o[3]);
        op[1] = make_float4(o[4], o[5], o[6], o[7]);
    }
}

// ---------------- launch ----------------
extern "C" void kernel_launch(void* const* d_in, const int* in_sizes, int n_in,
                              void* d_out, int out_size) {
    const float* x          = (const float*)d_in[0];
    const int*   edge_index = (const int*)d_in[1];
    const float* edge_attr  = (const float*)d_in[2];
    const float* Wl0  = (const float*)d_in[3];
    const float* bl0  = (const float*)d_in[4];
    const float* Wr0  = (const float*)d_in[5];
    const float* br0  = (const float*)d_in[6];
    const float* We0  = (const float*)d_in[7];
    const float* att0 = (const float*)d_in[8];
    const float* bias0= (const float*)d_in[9];
    const float* Wl1  = (const float*)d_in[10];
    const float* bl1  = (const float*)d_in[11];
    const float* Wr1  = (const float*)d_in[12];
    const float* br1  = (const float*)d_in[13];
    const float* We1  = (const float*)d_in[14];
    const float* att1 = (const float*)d_in[15];
    const float* bias1= (const float*)d_in[16];
    const float* Wmu  = (const float*)d_in[17];
    const float* bmu  = (const float*)d_in[18];

    const int E = in_sizes[1] / 2;
    const int n = in_sizes[0] / IND;
    const int* src = edge_index;
    const int* dst = edge_index + E;

    void *p_deg, *p_cnt, *p_loop, *p_xl, *p_xr, *p_h1, *p_h2;
    cudaGetSymbolAddress(&p_deg, g_deg);
    cudaGetSymbolAddress(&p_cnt, g_cnt);
    cudaGetSymbolAddress(&p_loop, g_loop);
    cudaGetSymbolAddress(&p_xl, g_xl);
    cudaGetSymbolAddress(&p_xr, g_xr);
    cudaGetSymbolAddress(&p_h1, g_h1);
    cudaGetSymbolAddress(&p_h2, g_h2);

    cudaMemsetAsync(p_deg, 0, (size_t)n * sizeof(int));
    cudaMemsetAsync(p_cnt, 0, (size_t)n * sizeof(int));
    cudaMemsetAsync(p_loop, 0, (size_t)n * EDIM * sizeof(float));

    cudaFuncSetAttribute(gemm_tf32_dual,
                         cudaFuncAttributeMaxDynamicSharedMemorySize,
                         GEMM_SMEM_BYTES);

    int eb = (E + 255) / 256;
    int sb = (n + 1023) / 1024;

    edge_accum_kernel<<<eb, 256>>>(dst, edge_attr, E);
    scan_block_kernel<<<sb, 1024>>>(n);
    scan_bsum_kernel<<<1, 64>>>(sb);
    scan_add_kernel<<<sb, 1024>>>(n);
    scatter_kernel<<<eb, 256>>>(dst, E);

    dim3 gdual(4, (n + 127) / 128);
    int aggBlocks = (n * 32 + 255) / 256;

    // ---- layer 0 ----
    gemm_tf32_dual<<<gdual, 256, GEMM_SMEM_BYTES>>>(x, Wl0, Wr0, bl0, br0,
                                   (float*)p_xl, (float*)p_xr, n, IND);
    gat_agg<<<aggBlocks, 256>>>((const float*)p_xl, (const float*)p_xr,
                                src, edge_attr, We0, att0, bias0,
                                (float*)p_h1, n);

    // ---- layer 1 ----
    gemm_tf32_dual<<<gdual, 256, GEMM_SMEM_BYTES>>>((const float*)p_h1, Wl1, Wr1, bl1, br1,
                                   (float*)p_xl, (float*)p_xr, n, CC);
    gat_agg<<<aggBlocks, 256>>>((const float*)p_xl, (const float*)p_xr,
                                src, edge_attr, We1, att1, bias1,
                                (float*)p_h2, n);

    // ---- final projection ----
    dim3 gmu((LAT + 63) / 64, (n + 63) / 64);
    sgemm_bias<<<gmu, 256>>>((const float*)p_h2, Wmu, bmu, (float*)d_out, n, CC, LAT);
}

// round 7
// speedup vs baseline: 3.0432x; 1.1407x over previous
#include <cuda_runtime.h>
#include <math.h>

#define NN 50000
#define EE 800000
#define IND 256
#define HH 4
#define CC 64
#define HC 256   // H*C
#define LAT 32
#define EDIM 3

typedef unsigned long long ull;

// ---------------- scratch (device globals; no allocation allowed) ----------------
__device__ int    g_deg[NN];
__device__ int    g_off[NN + 1];
__device__ int    g_cnt[NN];
__device__ float4 g_erec[EE];       // {src_as_float, ea0, ea1, ea2} in CSR order
__device__ int    g_bsum[64];
__device__ float  g_loop[NN * EDIM];
__device__ float  g_xl[NN * HC];
__device__ float  g_xr[NN * HC];
__device__ float  g_h1[NN * CC];
__device__ float  g_h2[NN * CC];

// ---------------- packed f32x2 helpers ----------------
__device__ __forceinline__ ull pk2(float lo, float hi) {
    ull r; asm("mov.b64 %0, {%1,%2};" : "=l"(r) : "f"(lo), "f"(hi)); return r;
}
__device__ __forceinline__ ull bc2(float x) { return pk2(x, x); }
__device__ __forceinline__ ull fma2(ull a, ull b, ull c) {
    ull d; asm("fma.rn.f32x2 %0, %1, %2, %3;" : "=l"(d) : "l"(a), "l"(b), "l"(c)); return d;
}
__device__ __forceinline__ ull add2(ull a, ull b) {
    ull d; asm("add.rn.f32x2 %0, %1, %2;" : "=l"(d) : "l"(a), "l"(b)); return d;
}
__device__ __forceinline__ ull mul2(ull a, ull b) {
    ull d; asm("mul.rn.f32x2 %0, %1, %2;" : "=l"(d) : "l"(a), "l"(b)); return d;
}
__device__ __forceinline__ void unpk2(ull v, float& lo, float& hi) {
    asm("mov.b64 {%0,%1}, %2;" : "=f"(lo), "=f"(hi) : "l"(v));
}

// ---------------- CSR build ----------------
__global__ void edge_accum_kernel(const int* __restrict__ dst,
                                  const float* __restrict__ ea, int e) {
    int i = blockIdx.x * blockDim.x + threadIdx.x;
    if (i < e) {
        int d = dst[i];
        atomicAdd(&g_deg[d], 1);
        atomicAdd(&g_loop[d * 3 + 0], ea[i * 3 + 0]);
        atomicAdd(&g_loop[d * 3 + 1], ea[i * 3 + 1]);
        atomicAdd(&g_loop[d * 3 + 2], ea[i * 3 + 2]);
    }
}

__global__ void scan_block_kernel(int n) {
    __shared__ int tmp[1024];
    int tid = threadIdx.x;
    int i = blockIdx.x * 1024 + tid;
    int v = (i < n) ? g_deg[i] : 0;
    tmp[tid] = v;
    __syncthreads();
    for (int d = 1; d < 1024; d <<= 1) {
        int t = (tid >= d) ? tmp[tid - d] : 0;
        __syncthreads();
        tmp[tid] += t;
        __syncthreads();
    }
    if (i < n) g_off[i + 1] = tmp[tid];
    if (tid == 1023) g_bsum[blockIdx.x] = tmp[tid];
    if (i == 0) g_off[0] = 0;
}

__global__ void scan_bsum_kernel(int nb) {
    __shared__ int tmp[64];
    int tid = threadIdx.x;
    int v = (tid < nb) ? g_bsum[tid] : 0;
    tmp[tid] = v;
    __syncthreads();
    for (int d = 1; d < 64; d <<= 1) {
        int t = (tid >= d) ? tmp[tid - d] : 0;
        __syncthreads();
        tmp[tid] += t;
        __syncthreads();
    }
    if (tid < nb) g_bsum[tid] = tmp[tid] - v;  // exclusive
}

// adds block prefix, finalizes loop_attr mean, zeroes g_cnt for scatter
__global__ void scan_add_kernel(int n) {
    int i = blockIdx.x * 1024 + threadIdx.x;
    if (i < n) {
        if (blockIdx.x > 0) g_off[i + 1] += g_bsum[blockIdx.x];
        float inv = 1.0f / (float)max(g_deg[i], 1);
        g_loop[i * 3 + 0] *= inv;
        g_loop[i * 3 + 1] *= inv;
        g_loop[i * 3 + 2] *= inv;
        g_cnt[i] = 0;
    }
}

// writes packed edge records {src, ea0, ea1, ea2} into CSR slots
__global__ void scatter_kernel(const int* __restrict__ dst,
                               const int* __restrict__ src,
                               const float* __restrict__ ea, int e) {
    int i = blockIdx.x * blockDim.x + threadIdx.x;
    if (i < e) {
        int d = dst[i];
        int p = g_off[d] + atomicAdd(&g_cnt[d], 1);
        g_erec[p] = make_float4(__int_as_float(src[i]),
                                ea[i * 3 + 0], ea[i * 3 + 1], ea[i * 3 + 2]);
    }
}

// ---------------- TF32 tensor-core GEMM, cp.async double-buffered ----------------
__device__ __forceinline__ unsigned f2tf32(float f) {
    unsigned u;
    asm("cvt.rna.tf32.f32 %0, %1;" : "=r"(u) : "f"(f));
    return u;
}

#define AS_STRIDE 36
#define BS_STRIDE 136
#define AS_STAGE (128 * AS_STRIDE)
#define BS_STAGE (32 * BS_STRIDE)
#define GEMM_SMEM_BYTES ((2 * AS_STAGE + 2 * BS_STAGE) * 4)

__device__ __forceinline__ void cp16(unsigned saddr, const float* g, unsigned srcsz) {
    asm volatile("cp.async.cg.shared.global [%0], [%1], 16, %2;"
                 :: "r"(saddr), "l"(g), "r"(srcsz));
}

__global__ __launch_bounds__(256) void gemm_tf32_dual(
    const float* __restrict__ A,
    const float* __restrict__ Bl, const float* __restrict__ Br,
    const float* __restrict__ bl, const float* __restrict__ br,
    float* __restrict__ Cl, float* __restrict__ Cr,
    int M, int K)
{
    extern __shared__ float sm[];
    float* Asm = sm;
    float* Bsm = sm + 2 * AS_STAGE;

    const int tid  = threadIdx.x;
    const int lane = tid & 31;
    const int warp = tid >> 5;
    const int g = lane >> 2;
    const int q = lane & 3;

    const int m_warp = (warp & 1) * 64;
    const int n_warp = (warp >> 1) * 32;

    const int row0 = blockIdx.y * 128;
    const int col0 = blockIdx.x * 128;
    const int half = (col0 >= 256);
    const float* Bp = half ? Br : Bl;
    const float* biasp = half ? br : bl;
    float* Cp = half ? Cr : Cl;
    const int bcol0 = col0 - half * 256;

    const int ar = tid >> 1;
    const int brow = tid >> 3;
    const int bc4 = (tid & 7) * 4;

    const unsigned asm_base = (unsigned)__cvta_generic_to_shared(Asm);
    const unsigned bsm_base = (unsigned)__cvta_generic_to_shared(Bsm);

    float acc[4][4][4] = {};
    const int nk = K >> 5;

    auto load_stage = [&](int stg, int k0) {
        const int garow = row0 + ar;
        const int carow = (garow < M) ? garow : (M - 1);
        const unsigned asz = (garow < M) ? 16u : 0u;
        const float* gA = A + (long)carow * K + k0;
        unsigned sA = asm_base + (stg * AS_STAGE + ar * AS_STRIDE) * 4;
        int cbase = (tid & 1) * 16;
        cp16(sA + (cbase + 0) * 4, gA + cbase + 0, asz);
        cp16(sA + (cbase + 4) * 4, gA + cbase + 4, asz);
        cp16(sA + (cbase + 8) * 4, gA + cbase + 8, asz);
        cp16(sA + (cbase + 12) * 4, gA + cbase + 12, asz);
        const float* gB = Bp + (long)(k0 + brow) * 256 + bcol0 + bc4;
        unsigned sB = bsm_base + (stg * BS_STAGE + brow * BS_STRIDE + bc4) * 4;
        cp16(sB, gB, 16u);
        cp16(sB + 32 * 4, gB + 32, 16u);
        cp16(sB + 64 * 4, gB + 64, 16u);
        cp16(sB + 96 * 4, gB + 96, 16u);
    };

    load_stage(0, 0);
    asm volatile("cp.async.commit_group;");

    for (int kt = 0; kt < nk; kt++) {
        if (kt + 1 < nk) load_stage((kt + 1) & 1, (kt + 1) * 32);
        asm volatile("cp.async.commit_group;");
        asm volatile("cp.async.wait_group 1;");
        __syncthreads();

        const float* As = Asm + (kt & 1) * AS_STAGE;
        const float* Bs = Bsm + (kt & 1) * BS_STAGE;

        #pragma unroll
        for (int kk = 0; kk < 32; kk += 8) {
            unsigned a[4][4], b[4][2];
            #pragma unroll
            for (int i = 0; i < 4; i++) {
                int r = m_warp + i * 16 + g;
                a[i][0] = f2tf32(As[r * AS_STRIDE + kk + q]);
                a[i][1] = f2tf32(As[(r + 8) * AS_STRIDE + kk + q]);
                a[i][2] = f2tf32(As[r * AS_STRIDE + kk + q + 4]);
                a[i][3] = f2tf32(As[(r + 8) * AS_STRIDE + kk + q + 4]);
            }
            #pragma unroll
            for (int j = 0; j < 4; j++) {
                int c = n_warp + j * 8 + g;
                b[j][0] = f2tf32(Bs[(kk + q) * BS_STRIDE + c]);
                b[j][1] = f2tf32(Bs[(kk + q + 4) * BS_STRIDE + c]);
            }
            #pragma unroll
            for (int i = 0; i < 4; i++)
                #pragma unroll
                for (int j = 0; j < 4; j++) {
                    asm volatile(
                        "mma.sync.aligned.m16n8k8.row.col.f32.tf32.tf32.f32 "
                        "{%0,%1,%2,%3}, {%4,%5,%6,%7}, {%8,%9}, {%0,%1,%2,%3};"
                        : "+f"(acc[i][j][0]), "+f"(acc[i][j][1]),
                          "+f"(acc[i][j][2]), "+f"(acc[i][j][3])
                        : "r"(a[i][0]), "r"(a[i][1]), "r"(a[i][2]), "r"(a[i][3]),
                          "r"(b[j][0]), "r"(b[j][1]));
                }
        }
        __syncthreads();
    }

    #pragma unroll
    for (int i = 0; i < 4; i++) {
        int r0 = row0 + m_warp + i * 16 + g;
        #pragma unroll
        for (int j = 0; j < 4; j++) {
            int cl = bcol0 + n_warp + j * 8 + 2 * q;
            float b0 = biasp[cl], b1 = biasp[cl + 1];
            if (r0 < M) {
                Cp[(long)r0 * 256 + cl]     = acc[i][j][0] + b0;
                Cp[(long)r0 * 256 + cl + 1] = acc[i][j][1] + b1;
            }
            if (r0 + 8 < M) {
                Cp[(long)(r0 + 8) * 256 + cl]     = acc[i][j][2] + b0;
                Cp[(long)(r0 + 8) * 256 + cl + 1] = acc[i][j][3] + b1;
            }
        }
    }
}

// ---------------- fp32 tiled SGEMM (final projection only) ----------------
__global__ void sgemm_bias(const float* __restrict__ A, const float* __restrict__ B,
                           const float* __restrict__ bias, float* __restrict__ C,
                           int M, int K, int Nc) {
    __shared__ float As[16][64];
    __shared__ float Bs[16][64 + 4];
    int tid = threadIdx.x;
    int tx = tid & 15, ty = tid >> 4;
    int row0 = blockIdx.y * 64, col0 = blockIdx.x * 64;
    float acc[4][4] = {};
    for (int k0 = 0; k0 < K; k0 += 16) {
        #pragma unroll
        for (int i = tid; i < 64 * 16; i += 256) {
            int m = i >> 4, k = i & 15;
            int r = row0 + m;
            As[k][m] = (r < M) ? A[(long)r * K + k0 + k] : 0.0f;
        }
        #pragma unroll
        for (int i = tid; i < 16 * 64; i += 256) {
            int k = i >> 6, c = i & 63;
            int cc = col0 + c;
            Bs[k][c] = (cc < Nc) ? B[(long)(k0 + k) * Nc + cc] : 0.0f;
        }
        __syncthreads();
        #pragma unroll
        for (int k = 0; k < 16; k++) {
            float a[4], b[4];
            #pragma unroll
            for (int i = 0; i < 4; i++) a[i] = As[k][ty * 4 + i];
            #pragma unroll
            for (int j = 0; j < 4; j++) b[j] = Bs[k][tx * 4 + j];
            #pragma unroll
            for (int i = 0; i < 4; i++)
                #pragma unroll
                for (int j = 0; j < 4; j++)
                    acc[i][j] += a[i] * b[j];
        }
        __syncthreads();
    }
    #pragma unroll
    for (int i = 0; i < 4; i++) {
        int r = row0 + ty * 4 + i;
        if (r >= M) continue;
        #pragma unroll
        for (int j = 0; j < 4; j++) {
            int c = col0 + tx * 4 + j;
            if (c < Nc) C[(long)r * Nc + c] = acc[i][j] + bias[c];
        }
    }
}

// ---------------- fused GATv2 attention + aggregation ----------------
// One warp per dst node; lane l owns 8 contiguous channels (4 f32x2 packs)
// of head l>>3. Two edges/iteration into independent online-softmax states,
// merged at the end. Edge meta = single LDG.128 record. Packed f32x2 math;
// leakyrelu(t,0.2) computed as 0.6t + 0.4|t|.
#define ABSMASK 0x7FFFFFFF7FFFFFFFULL

__global__ __launch_bounds__(256) void gat_agg(
        const float* __restrict__ xl, const float* __restrict__ xr,
        const float* __restrict__ We, const float* __restrict__ att,
        const float* __restrict__ bias, float* __restrict__ out,
        int n) {
    int warp = (blockIdx.x * blockDim.x + threadIdx.x) >> 5;
    int lane = threadIdx.x & 31;
    if (warp >= n) return;
    const int node = warp;
    const int base = ((lane >> 3) << 6) | ((lane & 7) << 3);
    const int b4 = base >> 2;

    ull we0[4], we1[4], we2[4], attv[4], xrv[4];
    {
        const float4* We4 = (const float4*)We;
        const float4* at4 = (const float4*)att;
        const float4* xr4 = (const float4*)(xr + (long)node * HC);
        *(float4*)&we0[0] = We4[b4];        *(float4*)&we0[2] = We4[b4 + 1];
        *(float4*)&we1[0] = We4[64 + b4];   *(float4*)&we1[2] = We4[64 + b4 + 1];
        *(float4*)&we2[0] = We4[128 + b4];  *(float4*)&we2[2] = We4[128 + b4 + 1];
        *(float4*)&attv[0] = at4[b4];       *(float4*)&attv[2] = at4[b4 + 1];
        *(float4*)&xrv[0] = xr4[b4];        *(float4*)&xrv[2] = xr4[b4 + 1];
    }
    const ull C06 = 0x3F19999A3F19999AULL;   // {0.6f, 0.6f}
    const ull C04 = 0x3ECCCCCD3ECCCCCDULL;   // {0.4f, 0.4f}

    const int o0 = g_off[node];
    const int deg = g_off[node + 1] - o0;

    auto fetch = [&](int pos, int& sn, float& e0, float& e1, float& e2) {
        if (pos < deg) {
            float4 rec = __ldg(&g_erec[o0 + pos]);
            sn = __float_as_int(rec.x);
            e0 = rec.y; e1 = rec.z; e2 = rec.w;
        } else { sn = node; e0 = 0.f; e1 = 0.f; e2 = 0.f; }
    };

    // per-state logit helper: returns warp-group-reduced logit
    auto logit = [&](const ull* cx, float e0, float e1, float e2) -> float {
        ull ea0 = bc2(e0), ea1 = bc2(e1), ea2 = bc2(e2);
        ull p2 = 0;
        #pragma unroll
        for (int j = 0; j < 4; j++) {
            ull bse = fma2(ea2, we2[j], fma2(ea1, we1[j], fma2(ea0, we0[j], xrv[j])));
            ull t = add2(cx[j], bse);
            ull l = fma2(C04, t & ABSMASK, mul2(C06, t));
            p2 = fma2(l, attv[j], p2);
        }
        float lo, hi;
        unpk2(p2, lo, hi);
        float p = lo + hi;
        p += __shfl_xor_sync(0xffffffffu, p, 1);
        p += __shfl_xor_sync(0xffffffffu, p, 2);
        p += __shfl_xor_sync(0xffffffffu, p, 4);
        return p;
    };

    // ---- state A seeded with the self-loop, state B empty ----
    ull accA[4], accB[4];
    float mA, sA, mB = -1e30f, sB = 0.f;
    {
        ull xvS[4];
        const float4* xp = (const float4*)(xl + (long)node * HC);
        *(float4*)&xvS[0] = xp[b4];
        *(float4*)&xvS[2] = xp[b4 + 1];
        mA = logit(xvS, g_loop[node * 3 + 0], g_loop[node * 3 + 1], g_loop[node * 3 + 2]);
        sA = 1.f;
        #pragma unroll
        for (int j = 0; j < 4; j++) { accA[j] = xvS[j]; accB[j] = 0; }
    }

    // ---- meta queue: pair 0 (current) + pair 1 (next) ----
    int snA0, snB0, snA1, snB1;
    float a00, a01, a02, b00, b01, b02;
    float a10, a11, a12, b10, b11, b12;
    fetch(0, snA0, a00, a01, a02);
    fetch(1, snB0, b00, b01, b02);
    ull xvA[4], xvB[4];
    {
        const float4* xp = (const float4*)(xl + (long)snA0 * HC);
        *(float4*)&xvA[0] = xp[b4]; *(float4*)&xvA[2] = xp[b4 + 1];
    }
    {
        const float4* xp = (const float4*)(xl + (long)snB0 * HC);
        *(float4*)&xvB[0] = xp[b4]; *(float4*)&xvB[2] = xp[b4 + 1];
    }
    fetch(2, snA1, a10, a11, a12);
    fetch(3, snB1, b10, b11, b12);

    for (int i = 0; i < deg; i += 2) {
        // snapshot current pair
        ull cxA[4], cxB[4];
        #pragma unroll
        for (int j = 0; j < 4; j++) { cxA[j] = xvA[j]; cxB[j] = xvB[j]; }
        const float cA0 = a00, cA1 = a01, cA2 = a02;
        const float cB0 = b00, cB1 = b01, cB2 = b02;
        const bool vB = (i + 1 < deg);

        // issue gathers for next pair (meta resolved last iteration)
        if (i + 2 < deg) {
            const float4* xp = (const float4*)(xl + (long)snA1 * HC);
            *(float4*)&xvA[0] = xp[b4]; *(float4*)&xvA[2] = xp[b4 + 1];
        }
        if (i + 3 < deg) {
            const float4* xp = (const float4*)(xl + (long)snB1 * HC);
            *(float4*)&xvB[0] = xp[b4]; *(float4*)&xvB[2] = xp[b4 + 1];
        }
        // rotate meta queue; fetch pair+2
        snA0 = snA1; a00 = a10; a01 = a11; a02 = a12;
        snB0 = snB1; b00 = b10; b01 = b11; b02 = b12;
        fetch(i + 4, snA1, a10, a11, a12);
        fetch(i + 5, snB1, b10, b11, b12);

        float pA = logit(cxA, cA0, cA1, cA2);
        float pB = logit(cxB, cB0, cB1, cB2);
        if (!vB) pB = -1e30f;

        // online softmax updates (independent states)
        float nmA = fmaxf(mA, pA), nmB = fmaxf(mB, pB);
        float scA = __expf(mA - nmA), wA = __expf(pA - nmA);
        float scB = __expf(mB - nmB), wB = __expf(pB - nmB);
        if (!vB) wB = 0.f;
        sA = sA * scA + wA; mA = nmA;
        sB = sB * scB + wB; mB = nmB;
        ull scA2 = bc2(scA), wA2 = bc2(wA);
        ull scB2 = bc2(scB), wB2 = bc2(wB);
        #pragma unroll
        for (int j = 0; j < 4; j++) {
            accA[j] = fma2(wA2, cxA[j], mul2(accA[j], scA2));
            accB[j] = fma2(wB2, cxB[j], mul2(accB[j], scB2));
        }
    }

    // ---- merge states, head mean, bias, relu ----
    float nm = fmaxf(mA, mB);
    float fA = __expf(mA - nm), fB = __expf(mB - nm);
    float inv = 1.f / (sA * fA + sB * fB);
    ull fA2 = bc2(fA * inv), fB2 = bc2(fB * inv);
    float r[8];
    #pragma unroll
    for (int j = 0; j < 4; j++) {
        ull v2 = add2(mul2(accA[j], fA2), mul2(accB[j], fB2));
        float lo, hi;
        unpk2(v2, lo, hi);
        lo += __shfl_xor_sync(0xffffffffu, lo, 8);
        hi += __shfl_xor_sync(0xffffffffu, hi, 8);
        lo += __shfl_xor_sync(0xffffffffu, lo, 16);
        hi += __shfl_xor_sync(0xffffffffu, hi, 16);
        r[2 * j] = lo; r[2 * j + 1] = hi;
    }
    if (lane < 8) {
        float o[8];
        #pragma unroll
        for (int j = 0; j < 8; j++)
            o[j] = fmaxf(0.25f * r[j] + bias[base + j], 0.f);
        float4* op = (float4*)(out + (long)node * CC + base);
        op[0] = make_float4(o[0], o[1], o[2], o[3]);
        op[1] = make_float4(o[4], o[5], o[6], o[7]);
    }
}

// ---------------- launch ----------------
extern "C" void kernel_launch(void* const* d_in, const int* in_sizes, int n_in,
                              void* d_out, int out_size) {
    const float* x          = (const float*)d_in[0];
    const int*   edge_index = (const int*)d_in[1];
    const float* edge_attr  = (const float*)d_in[2];
    const float* Wl0  = (const float*)d_in[3];
    const float* bl0  = (const float*)d_in[4];
    const float* Wr0  = (const float*)d_in[5];
    const float* br0  = (const float*)d_in[6];
    const float* We0  = (const float*)d_in[7];
    const float* att0 = (const float*)d_in[8];
    const float* bias0= (const float*)d_in[9];
    const float* Wl1  = (const float*)d_in[10];
    const float* bl1  = (const float*)d_in[11];
    const float* Wr1  = (const float*)d_in[12];
    const float* br1  = (const float*)d_in[13];
    const float* We1  = (const float*)d_in[14];
    const float* att1 = (const float*)d_in[15];
    const float* bias1= (const float*)d_in[16];
    const float* Wmu  = (const float*)d_in[17];
    const float* bmu  = (const float*)d_in[18];

    const int E = in_sizes[1] / 2;
    const int n = in_sizes[0] / IND;
    const int* src = edge_index;
    const int* dst = edge_index + E;

    void *p_deg, *p_loop, *p_xl, *p_xr, *p_h1, *p_h2;
    cudaGetSymbolAddress(&p_deg, g_deg);
    cudaGetSymbolAddress(&p_loop, g_loop);
    cudaGetSymbolAddress(&p_xl, g_xl);
    cudaGetSymbolAddress(&p_xr, g_xr);
    cudaGetSymbolAddress(&p_h1, g_h1);
    cudaGetSymbolAddress(&p_h2, g_h2);

    cudaMemsetAsync(p_deg, 0, (size_t)n * sizeof(int));
    cudaMemsetAsync(p_loop, 0, (size_t)n * EDIM * sizeof(float));

    cudaFuncSetAttribute(gemm_tf32_dual,
                         cudaFuncAttributeMaxDynamicSharedMemorySize,
                         GEMM_SMEM_BYTES);

    int eb = (E + 255) / 256;
    int sb = (n + 1023) / 1024;

    edge_accum_kernel<<<eb, 256>>>(dst, edge_attr, E);
    scan_block_kernel<<<sb, 1024>>>(n);
    scan_bsum_kernel<<<1, 64>>>(sb);
    scan_add_kernel<<<sb, 1024>>>(n);
    scatter_kernel<<<eb, 256>>>(dst, src, edge_attr, E);

    dim3 gdual(4, (n + 127) / 128);
    int aggBlocks = (n * 32 + 255) / 256;

    // ---- layer 0 ----
    gemm_tf32_dual<<<gdual, 256, GEMM_SMEM_BYTES>>>(x, Wl0, Wr0, bl0, br0,
                                   (float*)p_xl, (float*)p_xr, n, IND);
    gat_agg<<<aggBlocks, 256>>>((const float*)p_xl, (const float*)p_xr,
                                We0, att0, bias0, (float*)p_h1, n);

    // ---- layer 1 ----
    gemm_tf32_dual<<<gdual, 256, GEMM_SMEM_BYTES>>>((const float*)p_h1, Wl1, Wr1, bl1, br1,
                                   (float*)p_xl, (float*)p_xr, n, CC);
    gat_agg<<<aggBlocks, 256>>>((const float*)p_xl, (const float*)p_xr,
                                We1, att1, bias1, (float*)p_h2, n);

    // ---- final projection ----
    dim3 gmu((LAT + 63) / 64, (n + 63) / 64);
    sgemm_bias<<<gmu, 256>>>((const float*)p_h2, Wmu, bmu, (float*)d_out, n, CC, LAT);
}

// round 8
// speedup vs baseline: 3.0435x; 1.0001x over previous
#include <cuda_runtime.h>
#include <math.h>

#define NN 50000
#define EE 800000
#define IND 256
#define HH 4
#define CC 64
#define HC 256   // H*C
#define LAT 32
#define EDIM 3

typedef unsigned long long ull;

// ---------------- scratch (device globals; no allocation allowed) ----------------
__device__ int    g_deg[NN];
__device__ int    g_off[NN + 1];
__device__ int    g_cnt[NN];
__device__ float4 g_erec[EE];       // {src_as_float, ea0, ea1, ea2} in CSR order
__device__ int    g_bsum[64];
__device__ float  g_loop[NN * EDIM];
__device__ float  g_xl[NN * HC];
__device__ float  g_xr[NN * HC];
__device__ float  g_h1[NN * CC];
__device__ float  g_h2[NN * CC];

// ---------------- packed f32x2 helpers ----------------
__device__ __forceinline__ ull pk2(float lo, float hi) {
    ull r; asm("mov.b64 %0, {%1,%2};" : "=l"(r) : "f"(lo), "f"(hi)); return r;
}
__device__ __forceinline__ ull bc2(float x) { return pk2(x, x); }
__device__ __forceinline__ ull fma2(ull a, ull b, ull c) {
    ull d; asm("fma.rn.f32x2 %0, %1, %2, %3;" : "=l"(d) : "l"(a), "l"(b), "l"(c)); return d;
}
__device__ __forceinline__ ull add2(ull a, ull b) {
    ull d; asm("add.rn.f32x2 %0, %1, %2;" : "=l"(d) : "l"(a), "l"(b)); return d;
}
__device__ __forceinline__ ull mul2(ull a, ull b) {
    ull d; asm("mul.rn.f32x2 %0, %1, %2;" : "=l"(d) : "l"(a), "l"(b)); return d;
}
__device__ __forceinline__ void unpk2(ull v, float& lo, float& hi) {
    asm("mov.b64 {%0,%1}, %2;" : "=f"(lo), "=f"(hi) : "l"(v));
}

// ---------------- CSR build ----------------
__global__ void edge_accum_kernel(const int* __restrict__ dst,
                                  const float* __restrict__ ea, int e) {
    int i = blockIdx.x * blockDim.x + threadIdx.x;
    if (i < e) {
        int d = dst[i];
        atomicAdd(&g_deg[d], 1);
        atomicAdd(&g_loop[d * 3 + 0], ea[i * 3 + 0]);
        atomicAdd(&g_loop[d * 3 + 1], ea[i * 3 + 1]);
        atomicAdd(&g_loop[d * 3 + 2], ea[i * 3 + 2]);
    }
}

__global__ void scan_block_kernel(int n) {
    __shared__ int tmp[1024];
    int tid = threadIdx.x;
    int i = blockIdx.x * 1024 + tid;
    int v = (i < n) ? g_deg[i] : 0;
    tmp[tid] = v;
    __syncthreads();
    for (int d = 1; d < 1024; d <<= 1) {
        int t = (tid >= d) ? tmp[tid - d] : 0;
        __syncthreads();
        tmp[tid] += t;
        __syncthreads();
    }
    if (i < n) g_off[i + 1] = tmp[tid];
    if (tid == 1023) g_bsum[blockIdx.x] = tmp[tid];
    if (i == 0) g_off[0] = 0;
}

__global__ void scan_bsum_kernel(int nb) {
    __shared__ int tmp[64];
    int tid = threadIdx.x;
    int v = (tid < nb) ? g_bsum[tid] : 0;
    tmp[tid] = v;
    __syncthreads();
    for (int d = 1; d < 64; d <<= 1) {
        int t = (tid >= d) ? tmp[tid - d] : 0;
        __syncthreads();
        tmp[tid] += t;
        __syncthreads();
    }
    if (tid < nb) g_bsum[tid] = tmp[tid] - v;  // exclusive
}

// adds block prefix, finalizes loop_attr mean, zeroes g_cnt for scatter
__global__ void scan_add_kernel(int n) {
    int i = blockIdx.x * 1024 + threadIdx.x;
    if (i < n) {
        if (blockIdx.x > 0) g_off[i + 1] += g_bsum[blockIdx.x];
        float inv = 1.0f / (float)max(g_deg[i], 1);
        g_loop[i * 3 + 0] *= inv;
        g_loop[i * 3 + 1] *= inv;
        g_loop[i * 3 + 2] *= inv;
        g_cnt[i] = 0;
    }
}

// writes packed edge records {src, ea0, ea1, ea2} into CSR slots
__global__ void scatter_kernel(const int* __restrict__ dst,
                               const int* __restrict__ src,
                               const float* __restrict__ ea, int e) {
    int i = blockIdx.x * blockDim.x + threadIdx.x;
    if (i < e) {
        int d = dst[i];
        int p = g_off[d] + atomicAdd(&g_cnt[d], 1);
        g_erec[p] = make_float4(__int_as_float(src[i]),
                                ea[i * 3 + 0], ea[i * 3 + 1], ea[i * 3 + 2]);
    }
}

// ---------------- TF32 tensor-core GEMM, cp.async double-buffered ----------------
__device__ __forceinline__ unsigned f2tf32(float f) {
    unsigned u;
    asm("cvt.rna.tf32.f32 %0, %1;" : "=r"(u) : "f"(f));
    return u;
}

#define AS_STRIDE 36
#define BS_STRIDE 136
#define AS_STAGE (128 * AS_STRIDE)
#define BS_STAGE (32 * BS_STRIDE)
#define GEMM_SMEM_BYTES ((2 * AS_STAGE + 2 * BS_STAGE) * 4)

__device__ __forceinline__ void cp16(unsigned saddr, const float* g, unsigned srcsz) {
    asm volatile("cp.async.cg.shared.global [%0], [%1], 16, %2;"
                 :: "r"(saddr), "l"(g), "r"(srcsz));
}

__global__ __launch_bounds__(256) void gemm_tf32_dual(
    const float* __restrict__ A,
    const float* __restrict__ Bl, const float* __restrict__ Br,
    const float* __restrict__ bl, const float* __restrict__ br,
    float* __restrict__ Cl, float* __restrict__ Cr,
    int M, int K)
{
    extern __shared__ float sm[];
    float* Asm = sm;
    float* Bsm = sm + 2 * AS_STAGE;

    const int tid  = threadIdx.x;
    const int lane = tid & 31;
    const int warp = tid >> 5;
    const int g = lane >> 2;
    const int q = lane & 3;

    const int m_warp = (warp & 1) * 64;
    const int n_warp = (warp >> 1) * 32;

    const int row0 = blockIdx.y * 128;
    const int col0 = blockIdx.x * 128;
    const int half = (col0 >= 256);
    const float* Bp = half ? Br : Bl;
    const float* biasp = half ? br : bl;
    float* Cp = half ? Cr : Cl;
    const int bcol0 = col0 - half * 256;

    const int ar = tid >> 1;
    const int brow = tid >> 3;
    const int bc4 = (tid & 7) * 4;

    const unsigned asm_base = (unsigned)__cvta_generic_to_shared(Asm);
    const unsigned bsm_base = (unsigned)__cvta_generic_to_shared(Bsm);

    float acc[4][4][4] = {};
    const int nk = K >> 5;

    auto load_stage = [&](int stg, int k0) {
        const int garow = row0 + ar;
        const int carow = (garow < M) ? garow : (M - 1);
        const unsigned asz = (garow < M) ? 16u : 0u;
        const float* gA = A + (long)carow * K + k0;
        unsigned sA = asm_base + (stg * AS_STAGE + ar * AS_STRIDE) * 4;
        int cbase = (tid & 1) * 16;
        cp16(sA + (cbase + 0) * 4, gA + cbase + 0, asz);
        cp16(sA + (cbase + 4) * 4, gA + cbase + 4, asz);
        cp16(sA + (cbase + 8) * 4, gA + cbase + 8, asz);
        cp16(sA + (cbase + 12) * 4, gA + cbase + 12, asz);
        const float* gB = Bp + (long)(k0 + brow) * 256 + bcol0 + bc4;
        unsigned sB = bsm_base + (stg * BS_STAGE + brow * BS_STRIDE + bc4) * 4;
        cp16(sB, gB, 16u);
        cp16(sB + 32 * 4, gB + 32, 16u);
        cp16(sB + 64 * 4, gB + 64, 16u);
        cp16(sB + 96 * 4, gB + 96, 16u);
    };

    load_stage(0, 0);
    asm volatile("cp.async.commit_group;");

    for (int kt = 0; kt < nk; kt++) {
        if (kt + 1 < nk) load_stage((kt + 1) & 1, (kt + 1) * 32);
        asm volatile("cp.async.commit_group;");
        asm volatile("cp.async.wait_group 1;");
        __syncthreads();

        const float* As = Asm + (kt & 1) * AS_STAGE;
        const float* Bs = Bsm + (kt & 1) * BS_STAGE;

        #pragma unroll
        for (int kk = 0; kk < 32; kk += 8) {
            unsigned a[4][4], b[4][2];
            #pragma unroll
            for (int i = 0; i < 4; i++) {
                int r = m_warp + i * 16 + g;
                a[i][0] = f2tf32(As[r * AS_STRIDE + kk + q]);
                a[i][1] = f2tf32(As[(r + 8) * AS_STRIDE + kk + q]);
                a[i][2] = f2tf32(As[r * AS_STRIDE + kk + q + 4]);
                a[i][3] = f2tf32(As[(r + 8) * AS_STRIDE + kk + q + 4]);
            }
            #pragma unroll
            for (int j = 0; j < 4; j++) {
                int c = n_warp + j * 8 + g;
                b[j][0] = f2tf32(Bs[(kk + q) * BS_STRIDE + c]);
                b[j][1] = f2tf32(Bs[(kk + q + 4) * BS_STRIDE + c]);
            }
            #pragma unroll
            for (int i = 0; i < 4; i++)
                #pragma unroll
                for (int j = 0; j < 4; j++) {
                    asm volatile(
                        "mma.sync.aligned.m16n8k8.row.col.f32.tf32.tf32.f32 "
                        "{%0,%1,%2,%3}, {%4,%5,%6,%7}, {%8,%9}, {%0,%1,%2,%3};"
                        : "+f"(acc[i][j][0]), "+f"(acc[i][j][1]),
                          "+f"(acc[i][j][2]), "+f"(acc[i][j][3])
                        : "r"(a[i][0]), "r"(a[i][1]), "r"(a[i][2]), "r"(a[i][3]),
                          "r"(b[j][0]), "r"(b[j][1]));
                }
        }
        __syncthreads();
    }

    #pragma unroll
    for (int i = 0; i < 4; i++) {
        int r0 = row0 + m_warp + i * 16 + g;
        #pragma unroll
        for (int j = 0; j < 4; j++) {
            int cl = bcol0 + n_warp + j * 8 + 2 * q;
            float b0 = biasp[cl], b1 = biasp[cl + 1];
            if (r0 < M) {
                Cp[(long)r0 * 256 + cl]     = acc[i][j][0] + b0;
                Cp[(long)r0 * 256 + cl + 1] = acc[i][j][1] + b1;
            }
            if (r0 + 8 < M) {
                Cp[(long)(r0 + 8) * 256 + cl]     = acc[i][j][2] + b0;
                Cp[(long)(r0 + 8) * 256 + cl + 1] = acc[i][j][3] + b1;
            }
        }
    }
}

// ---------------- fp32 tiled SGEMM (final projection only) ----------------
__global__ void sgemm_bias(const float* __restrict__ A, const float* __restrict__ B,
                           const float* __restrict__ bias, float* __restrict__ C,
                           int M, int K, int Nc) {
    __shared__ float As[16][64];
    __shared__ float Bs[16][64 + 4];
    int tid = threadIdx.x;
    int tx = tid & 15, ty = tid >> 4;
    int row0 = blockIdx.y * 64, col0 = blockIdx.x * 64;
    float acc[4][4] = {};
    for (int k0 = 0; k0 < K; k0 += 16) {
        #pragma unroll
        for (int i = tid; i < 64 * 16; i += 256) {
            int m = i >> 4, k = i & 15;
            int r = row0 + m;
            As[k][m] = (r < M) ? A[(long)r * K + k0 + k] : 0.0f;
        }
        #pragma unroll
        for (int i = tid; i < 16 * 64; i += 256) {
            int k = i >> 6, c = i & 63;
            int cc = col0 + c;
            Bs[k][c] = (cc < Nc) ? B[(long)(k0 + k) * Nc + cc] : 0.0f;
        }
        __syncthreads();
        #pragma unroll
        for (int k = 0; k < 16; k++) {
            float a[4], b[4];
            #pragma unroll
            for (int i = 0; i < 4; i++) a[i] = As[k][ty * 4 + i];
            #pragma unroll
            for (int j = 0; j < 4; j++) b[j] = Bs[k][tx * 4 + j];
            #pragma unroll
            for (int i = 0; i < 4; i++)
                #pragma unroll
                for (int j = 0; j < 4; j++)
                    acc[i][j] += a[i] * b[j];
        }
        __syncthreads();
    }
    #pragma unroll
    for (int i = 0; i < 4; i++) {
        int r = row0 + ty * 4 + i;
        if (r >= M) continue;
        #pragma unroll
        for (int j = 0; j < 4; j++) {
            int c = col0 + tx * 4 + j;
            if (c < Nc) C[(long)r * Nc + c] = acc[i][j] + bias[c];
        }
    }
}

// ---------------- fused GATv2 attention + aggregation ----------------
// One warp per dst node; lane l owns 8 contiguous channels (4 f32x2 packs)
// of head l>>3. Two edges/iteration into independent online-softmax states,
// merged at the end. Edge meta = single LDG.128 record. Packed f32x2 math;
// leakyrelu(t,0.2) computed as 0.6t + 0.4|t|.
#define ABSMASK 0x7FFFFFFF7FFFFFFFULL

__global__ __launch_bounds__(256) void gat_agg(
        const float* __restrict__ xl, const float* __restrict__ xr,
        const float* __restrict__ We, const float* __restrict__ att,
        const float* __restrict__ bias, float* __restrict__ out,
        int n) {
    int warp = (blockIdx.x * blockDim.x + threadIdx.x) >> 5;
    int lane = threadIdx.x & 31;
    if (warp >= n) return;
    const int node = warp;
    const int base = ((lane >> 3) << 6) | ((lane & 7) << 3);
    const int b4 = base >> 2;

    ull we0[4], we1[4], we2[4], attv[4], xrv[4];
    {
        const float4* We4 = (const float4*)We;
        const float4* at4 = (const float4*)att;
        const float4* xr4 = (const float4*)(xr + (long)node * HC);
        *(float4*)&we0[0] = We4[b4];        *(float4*)&we0[2] = We4[b4 + 1];
        *(float4*)&we1[0] = We4[64 + b4];   *(float4*)&we1[2] = We4[64 + b4 + 1];
        *(float4*)&we2[0] = We4[128 + b4];  *(float4*)&we2[2] = We4[128 + b4 + 1];
        *(float4*)&attv[0] = at4[b4];       *(float4*)&attv[2] = at4[b4 + 1];
        *(float4*)&xrv[0] = xr4[b4];        *(float4*)&xrv[2] = xr4[b4 + 1];
    }
    const ull C06 = 0x3F19999A3F19999AULL;   // {0.6f, 0.6f}
    const ull C04 = 0x3ECCCCCD3ECCCCCDULL;   // {0.4f, 0.4f}

    const int o0 = g_off[node];
    const int deg = g_off[node + 1] - o0;

    auto fetch = [&](int pos, int& sn, float& e0, float& e1, float& e2) {
        if (pos < deg) {
            float4 rec = __ldg(&g_erec[o0 + pos]);
            sn = __float_as_int(rec.x);
            e0 = rec.y; e1 = rec.z; e2 = rec.w;
        } else { sn = node; e0 = 0.f; e1 = 0.f; e2 = 0.f; }
    };

    // per-state logit helper: returns warp-group-reduced logit
    auto logit = [&](const ull* cx, float e0, float e1, float e2) -> float {
        ull ea0 = bc2(e0), ea1 = bc2(e1), ea2 = bc2(e2);
        ull p2 = 0;
        #pragma unroll
        for (int j = 0; j < 4; j++) {
            ull bse = fma2(ea2, we2[j], fma2(ea1, we1[j], fma2(ea0, we0[j], xrv[j])));
            ull t = add2(cx[j], bse);
            ull l = fma2(C04, t & ABSMASK, mul2(C06, t));
            p2 = fma2(l, attv[j], p2);
        }
        float lo, hi;
        unpk2(p2, lo, hi);
        float p = lo + hi;
        p += __shfl_xor_sync(0xffffffffu, p, 1);
        p += __shfl_xor_sync(0xffffffffu, p, 2);
        p += __shfl_xor_sync(0xffffffffu, p, 4);
        return p;
    };

    // ---- state A seeded with the self-loop, state B empty ----
    ull accA[4], accB[4];
    float mA, sA, mB = -1e30f, sB = 0.f;
    {
        ull xvS[4];
        const float4* xp = (const float4*)(xl + (long)node * HC);
        *(float4*)&xvS[0] = xp[b4];
        *(float4*)&xvS[2] = xp[b4 + 1];
        mA = logit(xvS, g_loop[node * 3 + 0], g_loop[node * 3 + 1], g_loop[node * 3 + 2]);
        sA = 1.f;
        #pragma unroll
        for (int j = 0; j < 4; j++) { accA[j] = xvS[j]; accB[j] = 0; }
    }

    // ---- meta queue: pair 0 (current) + pair 1 (next) ----
    int snA0, snB0, snA1, snB1;
    float a00, a01, a02, b00, b01, b02;
    float a10, a11, a12, b10, b11, b12;
    fetch(0, snA0, a00, a01, a02);
    fetch(1, snB0, b00, b01, b02);
    ull xvA[4], xvB[4];
    {
        const float4* xp = (const float4*)(xl + (long)snA0 * HC);
        *(float4*)&xvA[0] = xp[b4]; *(float4*)&xvA[2] = xp[b4 + 1];
    }
    {
        const float4* xp = (const float4*)(xl + (long)snB0 * HC);
        *(float4*)&xvB[0] = xp[b4]; *(float4*)&xvB[2] = xp[b4 + 1];
    }
    fetch(2, snA1, a10, a11, a12);
    fetch(3, snB1, b10, b11, b12);

    for (int i = 0; i < deg; i += 2) {
        // snapshot current pair
        ull cxA[4], cxB[4];
        #pragma unroll
        for (int j = 0; j < 4; j++) { cxA[j] = xvA[j]; cxB[j] = xvB[j]; }
        const float cA0 = a00, cA1 = a01, cA2 = a02;
        const float cB0 = b00, cB1 = b01, cB2 = b02;
        const bool vB = (i + 1 < deg);

        // issue gathers for next pair (meta resolved last iteration)
        if (i + 2 < deg) {
            const float4* xp = (const float4*)(xl + (long)snA1 * HC);
            *(float4*)&xvA[0] = xp[b4]; *(float4*)&xvA[2] = xp[b4 + 1];
        }
        if (i + 3 < deg) {
            const float4* xp = (const float4*)(xl + (long)snB1 * HC);
            *(float4*)&xvB[0] = xp[b4]; *(float4*)&xvB[2] = xp[b4 + 1];
        }
        // rotate meta queue; fetch pair+2
        snA0 = snA1; a00 = a10; a01 = a11; a02 = a12;
        snB0 = snB1; b00 = b10; b01 = b11; b02 = b12;
        fetch(i + 4, snA1, a10, a11, a12);
        fetch(i + 5, snB1, b10, b11, b12);

        float pA = logit(cxA, cA0, cA1, cA2);
        float pB = logit(cxB, cB0, cB1, cB2);
        if (!vB) pB = -1e30f;

        // online softmax updates (independent states)
        float nmA = fmaxf(mA, pA), nmB = fmaxf(mB, pB);
        float scA = __expf(mA - nmA), wA = __expf(pA - nmA);
        float scB = __expf(mB - nmB), wB = __expf(pB - nmB);
        if (!vB) wB = 0.f;
        sA = sA * scA + wA; mA = nmA;
        sB = sB * scB + wB; mB = nmB;
        ull scA2 = bc2(scA), wA2 = bc2(wA);
        ull scB2 = bc2(scB), wB2 = bc2(wB);
        #pragma unroll
        for (int j = 0; j < 4; j++) {
            accA[j] = fma2(wA2, cxA[j], mul2(accA[j], scA2));
            accB[j] = fma2(wB2, cxB[j], mul2(accB[j], scB2));
        }
    }

    // ---- merge states, head mean, bias, relu ----
    float nm = fmaxf(mA, mB);
    float fA = __expf(mA - nm), fB = __expf(mB - nm);
    float inv = 1.f / (sA * fA + sB * fB);
    ull fA2 = bc2(fA * inv), fB2 = bc2(fB * inv);
    float r[8];
    #pragma unroll
    for (int j = 0; j < 4; j++) {
        ull v2 = add2(mul2(accA[j], fA2), mul2(accB[j], fB2));
        float lo, hi;
        unpk2(v2, lo, hi);
        lo += __shfl_xor_sync(0xffffffffu, lo, 8);
        hi += __shfl_xor_sync(0xffffffffu, hi, 8);
        lo += __shfl_xor_sync(0xffffffffu, lo, 16);
        hi += __shfl_xor_sync(0xffffffffu, hi, 16);
        r[2 * j] = lo; r[2 * j + 1] = hi;
    }
    if (lane < 8) {
        float o[8];
        #pragma unroll
        for (int j = 0; j < 8; j++)
            o[j] = fmaxf(0.25f * r[j] + bias[base + j], 0.f);
        float4* op = (float4*)(out + (long)node * CC + base);
        op[0] = make_float4(o[0], o[1], o[2], o[3]);
        op[1] = make_float4(o[4], o[5], o[6], o[7]);
    }
}

// ---------------- launch ----------------
extern "C" void kernel_launch(void* const* d_in, const int* in_sizes, int n_in,
                              void* d_out, int out_size) {
    const float* x          = (const float*)d_in[0];
    const int*   edge_index = (const int*)d_in[1];
    const float* edge_attr  = (const float*)d_in[2];
    const float* Wl0  = (const float*)d_in[3];
    const float* bl0  = (const float*)d_in[4];
    const float* Wr0  = (const float*)d_in[5];
    const float* br0  = (const float*)d_in[6];
    const float* We0  = (const float*)d_in[7];
    const float* att0 = (const float*)d_in[8];
    const float* bias0= (const float*)d_in[9];
    const float* Wl1  = (const float*)d_in[10];
    const float* bl1  = (const float*)d_in[11];
    const float* Wr1  = (const float*)d_in[12];
    const float* br1  = (const float*)d_in[13];
    const float* We1  = (const float*)d_in[14];
    const float* att1 = (const float*)d_in[15];
    const float* bias1= (const float*)d_in[16];
    const float* Wmu  = (const float*)d_in[17];
    const float* bmu  = (const float*)d_in[18];

    const int E = in_sizes[1] / 2;
    const int n = in_sizes[0] / IND;
    const int* src = edge_index;
    const int* dst = edge_index + E;

    void *p_deg, *p_loop, *p_xl, *p_xr, *p_h1, *p_h2;
    cudaGetSymbolAddress(&p_deg, g_deg);
    cudaGetSymbolAddress(&p_loop, g_loop);
    cudaGetSymbolAddress(&p_xl, g_xl);
    cudaGetSymbolAddress(&p_xr, g_xr);
    cudaGetSymbolAddress(&p_h1, g_h1);
    cudaGetSymbolAddress(&p_h2, g_h2);

    cudaMemsetAsync(p_deg, 0, (size_t)n * sizeof(int));
    cudaMemsetAsync(p_loop, 0, (size_t)n * EDIM * sizeof(float));

    cudaFuncSetAttribute(gemm_tf32_dual,
                         cudaFuncAttributeMaxDynamicSharedMemorySize,
                         GEMM_SMEM_BYTES);

    int eb = (E + 255) / 256;
    int sb = (n + 1023) / 1024;

    edge_accum_kernel<<<eb, 256>>>(dst, edge_attr, E);
    scan_block_kernel<<<sb, 1024>>>(n);
    scan_bsum_kernel<<<1, 64>>>(sb);
    scan_add_kernel<<<sb, 1024>>>(n);
    scatter_kernel<<<eb, 256>>>(dst, src, edge_attr, E);

    dim3 gdual(4, (n + 127) / 128);
    int aggBlocks = (n * 32 + 255) / 256;

    // ---- layer 0 ----
    gemm_tf32_dual<<<gdual, 256, GEMM_SMEM_BYTES>>>(x, Wl0, Wr0, bl0, br0,
                                   (float*)p_xl, (float*)p_xr, n, IND);
    gat_agg<<<aggBlocks, 256>>>((const float*)p_xl, (const float*)p_xr,
                                We0, att0, bias0, (float*)p_h1, n);

    // ---- layer 1 ----
    gemm_tf32_dual<<<gdual, 256, GEMM_SMEM_BYTES>>>((const float*)p_h1, Wl1, Wr1, bl1, br1,
                                   (float*)p_xl, (float*)p_xr, n, CC);
    gat_agg<<<aggBlocks, 256>>>((const float*)p_xl, (const float*)p_xr,
                                We1, att1, bias1, (float*)p_h2, n);

    // ---- final projection ----
    dim3 gmu((LAT + 63) / 64, (n + 63) / 64);
    sgemm_bias<<<gmu, 256>>>((const float*)p_h2, Wmu, bmu, (float*)d_out, n, CC, LAT);
}